// round 10
// baseline (speedup 1.0000x reference)
#include <cuda_runtime.h>
#include <cuda_bf16.h>
#include <cstdint>

// ---------------------------------------------------------------------------
// GPT-style transformer forward. GEMMs on tensor cores via mma.sync (bf16x3
// split for fp32-like accuracy); attention fp32 flash-style SIMT.
// B=4, T=1024, D=1024, H=16, HS=64, L=8, FF=4096, V=8192
// ---------------------------------------------------------------------------

#define Dm   1024
#define FFm  4096
#define Vm   8192
#define Hm   16
#define HSm  64
#define Lm   8
#define Bm_  4
#define Tm   1024
#define Mrows (Bm_ * Tm)   // 4096
#define QKVN 3072

// fp32 activation scratch
__device__ float g_h  [Mrows * Dm];
__device__ float g_hn [Mrows * Dm];
__device__ float g_qkv[Mrows * QKVN];

// bf16 split activation scratch
__device__ __nv_bfloat16 g_ah[Mrows * Dm],  g_al[Mrows * Dm];
__device__ __nv_bfloat16 g_fh[Mrows * FFm], g_fl[Mrows * FFm];

// bf16 split weight scratch ([N][K] transposed layout), reused per layer
__device__ __nv_bfloat16 g_wqkvh[QKVN * Dm], g_wqkvl[QKVN * Dm];
__device__ __nv_bfloat16 g_oh[Dm * Dm],  g_ol[Dm * Dm];
__device__ __nv_bfloat16 g_1h[Dm * FFm], g_1l[Dm * FFm];
__device__ __nv_bfloat16 g_2h[Dm * FFm], g_2l[Dm * FFm];
__device__ __nv_bfloat16 g_lh[Dm * Vm],  g_ll[Dm * Vm];

// ---------------------------------------------------------------------------
// helpers
// ---------------------------------------------------------------------------
__device__ __forceinline__ uint32_t smem_u32(const void* p) {
    uint32_t a;
    asm("{ .reg .u64 t; cvta.to.shared.u64 t, %1; cvt.u32.u64 %0, t; }"
        : "=r"(a) : "l"(p));
    return a;
}

__device__ __forceinline__ void split_bf16(float f, __nv_bfloat16& h, __nv_bfloat16& l) {
    h = __float2bfloat16(f);
    l = __float2bfloat16(f - __bfloat162float(h));
}

__device__ __forceinline__ void ldsm4(uint32_t* r, uint32_t addr) {
    asm volatile("ldmatrix.sync.aligned.m8n8.x4.shared.b16 {%0,%1,%2,%3}, [%4];\n"
                 : "=r"(r[0]), "=r"(r[1]), "=r"(r[2]), "=r"(r[3]) : "r"(addr));
}

__device__ __forceinline__ void mma16816(float* c, const uint32_t* a, const uint32_t* b) {
    asm volatile(
        "mma.sync.aligned.m16n8k16.row.col.f32.bf16.bf16.f32 "
        "{%0,%1,%2,%3}, {%4,%5,%6,%7}, {%8,%9}, {%0,%1,%2,%3};\n"
        : "+f"(c[0]), "+f"(c[1]), "+f"(c[2]), "+f"(c[3])
        : "r"(a[0]), "r"(a[1]), "r"(a[2]), "r"(a[3]), "r"(b[0]), "r"(b[1]));
}

// ---------------------------------------------------------------------------
// Embedding: h[row] = tok_embd[x[row]] + pos_embd[x[row]]   (pos quirk!)
// ---------------------------------------------------------------------------
__global__ void k_embed(const int* __restrict__ x, const float* __restrict__ tok,
                        const float* __restrict__ pos, float* __restrict__ out)
{
    int row = blockIdx.x;
    int t = x[row];
    const float4* te = (const float4*)(tok + (size_t)t * Dm);
    const float4* pe = (const float4*)(pos + (size_t)t * Dm);
    float4* o = (float4*)(out + (size_t)row * Dm);
    int i = threadIdx.x;
    float4 a = te[i], b = pe[i];
    o[i] = make_float4(a.x + b.x, a.y + b.y, a.z + b.z, a.w + b.w);
}

// ---------------------------------------------------------------------------
// LayerNorm over D=1024 + fused bf16 hi/lo split of the output.
// ---------------------------------------------------------------------------
__global__ void k_ln(const float* __restrict__ in, const float* __restrict__ gw,
                     const float* __restrict__ bw, float* __restrict__ out,
                     __nv_bfloat16* __restrict__ oh, __nv_bfloat16* __restrict__ ol)
{
    __shared__ float red[8];
    int row = blockIdx.x;
    int c = threadIdx.x * 4;
    const float* xr = in + (size_t)row * Dm;
    float4 xv = *(const float4*)(xr + c);
    float s = xv.x + xv.y + xv.z + xv.w;
    #pragma unroll
    for (int o = 16; o; o >>= 1) s += __shfl_xor_sync(0xffffffffu, s, o);
    int wid = threadIdx.x >> 5, lid = threadIdx.x & 31;
    if (lid == 0) red[wid] = s;
    __syncthreads();
    float tot = 0.f;
    #pragma unroll
    for (int i = 0; i < 8; i++) tot += red[i];
    float mean = tot * (1.0f / Dm);
    float d0 = xv.x - mean, d1 = xv.y - mean, d2 = xv.z - mean, d3 = xv.w - mean;
    float s2 = d0*d0 + d1*d1 + d2*d2 + d3*d3;
    __syncthreads();
    #pragma unroll
    for (int o = 16; o; o >>= 1) s2 += __shfl_xor_sync(0xffffffffu, s2, o);
    if (lid == 0) red[wid] = s2;
    __syncthreads();
    float v2 = 0.f;
    #pragma unroll
    for (int i = 0; i < 8; i++) v2 += red[i];
    float rstd = rsqrtf(v2 * (1.0f / Dm) + 1e-5f);
    float4 gv = *(const float4*)(gw + c);
    float4 bv = *(const float4*)(bw + c);
    float4 ov = make_float4(d0 * rstd * gv.x + bv.x, d1 * rstd * gv.y + bv.y,
                            d2 * rstd * gv.z + bv.z, d3 * rstd * gv.w + bv.w);
    size_t off = (size_t)row * Dm + c;
    *(float4*)(out + off) = ov;
    __nv_bfloat16 h0, l0, h1, l1, h2, l2, h3, l3;
    split_bf16(ov.x, h0, l0); split_bf16(ov.y, h1, l1);
    split_bf16(ov.z, h2, l2); split_bf16(ov.w, h3, l3);
    *(__nv_bfloat162*)(oh + off)     = __halves2bfloat162(h0, h1);
    *(__nv_bfloat162*)(oh + off + 2) = __halves2bfloat162(h2, h3);
    *(__nv_bfloat162*)(ol + off)     = __halves2bfloat162(l0, l1);
    *(__nv_bfloat162*)(ol + off + 2) = __halves2bfloat162(l2, l3);
}

// ---------------------------------------------------------------------------
// Weight convert: qkv (H,D,HS) -> packed [3072][1024] bf16 hi/lo
// ---------------------------------------------------------------------------
__global__ void k_conv_qkv(const float* __restrict__ wq, const float* __restrict__ wk,
                           const float* __restrict__ wv,
                           __nv_bfloat16* __restrict__ oh,
                           __nv_bfloat16* __restrict__ ol)
{
    __shared__ float t[64][65];
    int h = blockIdx.y;
    int d0 = blockIdx.x << 6;
    int m = blockIdx.z;
    const float* src = (m == 0) ? wq : (m == 1) ? wk : wv;

    const float* base = src + ((size_t)h << 16) + ((size_t)d0 << 6);
    for (int i = threadIdx.x; i < 1024; i += 256) {
        int di = i >> 4, e4 = (i & 15) << 2;
        float4 v = *(const float4*)(base + ((size_t)di << 6) + e4);
        t[di][e4] = v.x; t[di][e4+1] = v.y; t[di][e4+2] = v.z; t[di][e4+3] = v.w;
    }
    __syncthreads();
    for (int i = threadIdx.x; i < 2048; i += 256) {
        int e = i >> 5, d2 = (i & 31) << 1;
        __nv_bfloat16 h0, l0, h1, l1;
        split_bf16(t[d2][e], h0, l0);
        split_bf16(t[d2 + 1][e], h1, l1);
        size_t off = ((size_t)(m * 1024 + h * 64 + e) << 10) + d0 + d2;
        *(__nv_bfloat162*)(oh + off) = __halves2bfloat162(h0, h1);
        *(__nv_bfloat162*)(ol + off) = __halves2bfloat162(l0, l1);
    }
}

// ---------------------------------------------------------------------------
// Weight convert (transpose): in [Kd,Nd] fp32 -> out [Nd][Kd] bf16 hi/lo
// ---------------------------------------------------------------------------
__global__ void k_conv_t(const float* __restrict__ in,
                         __nv_bfloat16* __restrict__ oh,
                         __nv_bfloat16* __restrict__ ol, int Kd, int Nd)
{
    __shared__ float t[64][65];
    int k0 = blockIdx.y << 6, n0 = blockIdx.x << 6;
    for (int i = threadIdx.x; i < 1024; i += 256) {
        int r = i >> 4, c4 = (i & 15) << 2;
        float4 v = *(const float4*)(in + (size_t)(k0 + r) * Nd + n0 + c4);
        t[r][c4] = v.x; t[r][c4+1] = v.y; t[r][c4+2] = v.z; t[r][c4+3] = v.w;
    }
    __syncthreads();
    for (int i = threadIdx.x; i < 2048; i += 256) {
        int n = i >> 5, k2 = (i & 31) << 1;
        __nv_bfloat16 h0, l0, h1, l1;
        split_bf16(t[k2][n], h0, l0);
        split_bf16(t[k2 + 1][n], h1, l1);
        size_t off = (size_t)(n0 + n) * Kd + k0 + k2;
        *(__nv_bfloat162*)(oh + off) = __halves2bfloat162(h0, h1);
        *(__nv_bfloat162*)(ol + off) = __halves2bfloat162(l0, l1);
    }
}

// ---------------------------------------------------------------------------
// Tensor-core GEMM (mma.sync, bf16x3):
// C[M,N] = A[M,K] * B^T  (A as [M][K] hi/lo; B as [N][K] hi/lo)
// 128x128 CTA tile, BK=32, 128 threads (4 warps, 64x64 warp tiles),
// double-buffered cp.async. Single rb register set (reg relief).
// ---------------------------------------------------------------------------
#define BK 32
#define SROW 40                       // bf16 elems per smem row
#define TILE_BYTES (128 * SROW * 2)   // 10240
#define STAGE_BYTES (4 * TILE_BYTES)  // 40960
#define GEMM_SMEM (2 * STAGE_BYTES)   // 81920
#define GT 128                        // gemm threads

__device__ __forceinline__ void issue_stage(
    uint32_t sb, int stage,
    const __nv_bfloat16* Ah, const __nv_bfloat16* Al,
    const __nv_bfloat16* Bh, const __nv_bfloat16* Bl,
    int m0, int n0, int kc, int K, int tid)
{
    uint32_t sbase = sb + stage * STAGE_BYTES;
    #pragma unroll
    for (int i = 0; i < 16; i++) {
        int id = (i << 7) + tid;          // 0..2047
        int tile = id >> 9;               // 0..3 : AH AL BH BL
        int r = (id >> 2) & 127;
        int c = id & 3;                   // 16B chunk within 64B row data
        const __nv_bfloat16* src =
            (tile == 0) ? Ah : (tile == 1) ? Al : (tile == 2) ? Bh : Bl;
        int rowg = ((tile < 2) ? m0 : n0) + r;
        const void* g = src + (size_t)rowg * K + kc + (c << 3);
        uint32_t s = sbase + tile * TILE_BYTES + r * (SROW * 2) + (c << 4);
        asm volatile("cp.async.cg.shared.global [%0], [%1], 16;\n"
                     :: "r"(s), "l"(g));
    }
}

__global__ __launch_bounds__(GT, 2)
void k_gemm_mma(const __nv_bfloat16* __restrict__ Ah, const __nv_bfloat16* __restrict__ Al,
                const __nv_bfloat16* __restrict__ Bh, const __nv_bfloat16* __restrict__ Bl,
                const float* __restrict__ bias, const float* __restrict__ res,
                float* __restrict__ C,
                __nv_bfloat16* __restrict__ Ch, __nv_bfloat16* __restrict__ Cl,
                int M, int N, int K, int relu)
{
    extern __shared__ __align__(128) char sm2[];
    uint32_t sb = smem_u32(sm2);
    int tid = threadIdx.x;
    int lane = tid & 31, wid = tid >> 5;
    int wm = (wid & 1) << 6;    // warp M offset (0/64)
    int wn = (wid >> 1) << 6;   // warp N offset (0/64)
    int m0 = blockIdx.y << 7, n0 = blockIdx.x << 7;

    float acc[4][8][4];
    #pragma unroll
    for (int i = 0; i < 4; i++)
        #pragma unroll
        for (int j = 0; j < 8; j++)
            #pragma unroll
            for (int k = 0; k < 4; k++) acc[i][j][k] = 0.f;

    issue_stage(sb, 0, Ah, Al, Bh, Bl, m0, n0, 0, K, tid);
    asm volatile("cp.async.commit_group;\n" ::: "memory");
    issue_stage(sb, 1, Ah, Al, Bh, Bl, m0, n0, BK, K, tid);
    asm volatile("cp.async.commit_group;\n" ::: "memory");

    // ldmatrix lane address components
    int a_row = ((lane >> 3) & 1) * 8 + (lane & 7);
    int a_k   = (lane >> 4) << 3;
    int b_row = ((lane >> 4) << 3) + (lane & 7);
    int b_k   = ((lane >> 3) & 1) << 3;

    int niter = K / BK;
    for (int it = 0; it < niter; it++) {
        asm volatile("cp.async.wait_group 1;\n" ::: "memory");
        __syncthreads();
        int stage = it & 1;
        uint32_t st = sb + stage * STAGE_BYTES;
        #pragma unroll
        for (int ks = 0; ks < 2; ks++) {
            uint32_t ra[4][4], rb[4][4];
            uint32_t aoffH[4], boffH[4];
            #pragma unroll
            for (int i = 0; i < 4; i++)
                aoffH[i] = st + ((wm + i * 16 + a_row) * SROW + ks * 16 + a_k) * 2;
            #pragma unroll
            for (int j2 = 0; j2 < 4; j2++)
                boffH[j2] = st + 2 * TILE_BYTES +
                            ((wn + j2 * 16 + b_row) * SROW + ks * 16 + b_k) * 2;
            // A-hi, B-hi
            #pragma unroll
            for (int i = 0; i < 4; i++) ldsm4(ra[i], aoffH[i]);
            #pragma unroll
            for (int j2 = 0; j2 < 4; j2++) ldsm4(rb[j2], boffH[j2]);
            // pass 0: Ah * Bh
            #pragma unroll
            for (int i = 0; i < 4; i++)
                #pragma unroll
                for (int j2 = 0; j2 < 4; j2++) {
                    mma16816(acc[i][j2 * 2 + 0], ra[i], &rb[j2][0]);
                    mma16816(acc[i][j2 * 2 + 1], ra[i], &rb[j2][2]);
                }
            // A-lo (reuse ra)
            #pragma unroll
            for (int i = 0; i < 4; i++) ldsm4(ra[i], aoffH[i] + TILE_BYTES);
            // pass 1: Al * Bh
            #pragma unroll
            for (int i = 0; i < 4; i++)
                #pragma unroll
                for (int j2 = 0; j2 < 4; j2++) {
                    mma16816(acc[i][j2 * 2 + 0], ra[i], &rb[j2][0]);
                    mma16816(acc[i][j2 * 2 + 1], ra[i], &rb[j2][2]);
                }
            // A-hi again, B-lo (reuse ra, rb)
            #pragma unroll
            for (int i = 0; i < 4; i++) ldsm4(ra[i], aoffH[i]);
            #pragma unroll
            for (int j2 = 0; j2 < 4; j2++) ldsm4(rb[j2], boffH[j2] + TILE_BYTES);
            // pass 2: Ah * Bl
            #pragma unroll
            for (int i = 0; i < 4; i++)
                #pragma unroll
                for (int j2 = 0; j2 < 4; j2++) {
                    mma16816(acc[i][j2 * 2 + 0], ra[i], &rb[j2][0]);
                    mma16816(acc[i][j2 * 2 + 1], ra[i], &rb[j2][2]);
                }
        }
        __syncthreads();
        if (it + 2 < niter)
            issue_stage(sb, stage, Ah, Al, Bh, Bl, m0, n0, (it + 2) * BK, K, tid);
        asm volatile("cp.async.commit_group;\n" ::: "memory");
    }

    // Epilogue: thread (g,tg) holds rows g,g+8, cols 2*tg..+1 of each m16n8 tile
    int g = lane >> 2, tg = (lane & 3) << 1;
    #pragma unroll
    for (int i = 0; i < 4; i++) {
        int r0 = m0 + wm + i * 16 + g;
        #pragma unroll
        for (int j = 0; j < 8; j++) {
            int col = n0 + wn + j * 8 + tg;
            float v00 = acc[i][j][0], v01 = acc[i][j][1];
            float v10 = acc[i][j][2], v11 = acc[i][j][3];
            if (bias) {
                float2 bb = *(const float2*)(bias + col);
                v00 += bb.x; v01 += bb.y; v10 += bb.x; v11 += bb.y;
            }
            if (relu) {
                v00 = fmaxf(v00, 0.f); v01 = fmaxf(v01, 0.f);
                v10 = fmaxf(v10, 0.f); v11 = fmaxf(v11, 0.f);
            }
            size_t o0 = (size_t)r0 * N + col;
            size_t o1 = o0 + (size_t)8 * N;
            if (Ch) {
                __nv_bfloat16 h0, l0, h1, l1;
                split_bf16(v00, h0, l0); split_bf16(v01, h1, l1);
                *(__nv_bfloat162*)(Ch + o0) = __halves2bfloat162(h0, h1);
                *(__nv_bfloat162*)(Cl + o0) = __halves2bfloat162(l0, l1);
                split_bf16(v10, h0, l0); split_bf16(v11, h1, l1);
                *(__nv_bfloat162*)(Ch + o1) = __halves2bfloat162(h0, h1);
                *(__nv_bfloat162*)(Cl + o1) = __halves2bfloat162(l0, l1);
            } else {
                if (res) {
                    float2 r0v = *(const float2*)(res + o0);
                    float2 r1v = *(const float2*)(res + o1);
                    v00 += r0v.x; v01 += r0v.y; v10 += r1v.x; v11 += r1v.y;
                }
                *(float2*)(C + o0) = make_float2(v00, v01);
                *(float2*)(C + o1) = make_float2(v10, v11);
            }
        }
    }
}

// ---------------------------------------------------------------------------
// Causal attention, flash-style (fp32 SIMT), conflict-aware layout:
// all tiles row-major; S via inner product; softmax 4 threads/row.
// Block = (b, h, 64-query tile). Reads packed qkv [M][3072]; writes bf16 split.
// ---------------------------------------------------------------------------
#define KSTR 65   // K tile row stride (floats), scalar access, 2-way max
#define ATT_SMEM ((3 * 64 * 68 + 64 * KSTR + 192) * 4)

__global__ __launch_bounds__(256)
void k_attn(const float* __restrict__ QKV,
            __nv_bfloat16* __restrict__ Oh, __nv_bfloat16* __restrict__ Ol)
{
    extern __shared__ __align__(16) float smA[];
    float* Qs   = smA;                       // [64][68] row-major, pre-scaled
    float* Vs   = smA + 64 * 68;             // [64][68] row-major
    float* Ss   = smA + 2 * 64 * 68;         // [64][68]
    float* Ks   = smA + 3 * 64 * 68;         // [64][KSTR] row-major (scalar)
    float* mRow = smA + 3 * 64 * 68 + 64 * KSTR;
    float* sRow = mRow + 64;
    float* fRow = sRow + 64;

    int qt = blockIdx.x;
    int bh = blockIdx.y;
    int b = bh >> 4, h = bh & 15;
    int tid = threadIdx.x;
    int tx = tid & 15, ty = tid >> 4;
    size_t rbase = (size_t)b * Tm;
    const float* Q  = QKV + h * HSm;
    const float* Kx = QKV + 1024 + h * HSm;
    const float* Vx = QKV + 2048 + h * HSm;

    for (int i = tid; i < 1024; i += 256) {
        int r = i >> 4, c = (i & 15) << 2;
        float4 qv = *(const float4*)(Q + (rbase + qt * 64 + r) * QKVN + c);
        *(float4*)&Qs[r * 68 + c] = make_float4(qv.x * 0.125f, qv.y * 0.125f,
                                                qv.z * 0.125f, qv.w * 0.125f);
    }
    if (tid < 64) { mRow[tid] = -1e30f; sRow[tid] = 0.f; }

    float acc[4][4] = {};
    int srow = tid >> 2, ssub = tid & 3;     // softmax mapping: 4 thr/row

    for (int kt = 0; kt <= qt; kt++) {
        __syncthreads();   // prev PV done / state visible
        for (int i = tid; i < 1024; i += 256) {
            int r = i >> 4, c = (i & 15) << 2;
            float4 kv = *(const float4*)(Kx + (rbase + kt * 64 + r) * QKVN + c);
            Ks[r * KSTR + c + 0] = kv.x;
            Ks[r * KSTR + c + 1] = kv.y;
            Ks[r * KSTR + c + 2] = kv.z;
            Ks[r * KSTR + c + 3] = kv.w;
            float4 vv = *(const float4*)(Vx + (rbase + kt * 64 + r) * QKVN + c);
            *(float4*)&Vs[r * 68 + c] = vv;
        }
        __syncthreads();

        // S = Q K^T, inner product over e (row-major both sides)
        float sc[4][4] = {};
        #pragma unroll 4
        for (int e = 0; e < 64; e += 4) {
            float4 q0 = *(const float4*)&Qs[((ty << 2) + 0) * 68 + e];
            float4 q1 = *(const float4*)&Qs[((ty << 2) + 1) * 68 + e];
            float4 q2 = *(const float4*)&Qs[((ty << 2) + 2) * 68 + e];
            float4 q3 = *(const float4*)&Qs[((ty << 2) + 3) * 68 + e];
            #pragma unroll
            for (int j = 0; j < 4; j++) {
                const float* kr = &Ks[((tx << 2) + j) * KSTR + e];
                float k0 = kr[0], k1 = kr[1], k2 = kr[2], k3 = kr[3];
                sc[0][j] += q0.x * k0 + q0.y * k1 + q0.z * k2 + q0.w * k3;
                sc[1][j] += q1.x * k0 + q1.y * k1 + q1.z * k2 + q1.w * k3;
                sc[2][j] += q2.x * k0 + q2.y * k1 + q2.z * k2 + q2.w * k3;
                sc[3][j] += q3.x * k0 + q3.y * k1 + q3.z * k2 + q3.w * k3;
            }
        }
        #pragma unroll
        for (int i = 0; i < 4; i++)
            *(float4*)&Ss[((ty << 2) + i) * 68 + (tx << 2)] =
                make_float4(sc[i][0], sc[i][1], sc[i][2], sc[i][3]);
        __syncthreads();

        // Online softmax: 4 threads per row, 16 elems each
        {
            int lim = (kt == qt) ? srow : 63;
            float mOld = mRow[srow];
            float mx = -1e30f;
            #pragma unroll
            for (int t = 0; t < 16; t++) {
                int j = (ssub << 4) + t;
                if (j <= lim) mx = fmaxf(mx, Ss[srow * 68 + j]);
            }
            mx = fmaxf(mx, __shfl_xor_sync(0xffffffffu, mx, 1));
            mx = fmaxf(mx, __shfl_xor_sync(0xffffffffu, mx, 2));
            mx = fmaxf(mx, mOld);
            float sum = 0.f;
            #pragma unroll
            for (int t = 0; t < 16; t++) {
                int j = (ssub << 4) + t;
                float p = (j <= lim) ? __expf(Ss[srow * 68 + j] - mx) : 0.f;
                Ss[srow * 68 + j] = p;
                sum += p;
            }
            sum += __shfl_xor_sync(0xffffffffu, sum, 1);
            sum += __shfl_xor_sync(0xffffffffu, sum, 2);
            if (ssub == 0) {
                float f = __expf(mOld - mx);
                mRow[srow] = mx;
                sRow[srow] = sRow[srow] * f + sum;
                fRow[srow] = f;
            }
        }
        __syncthreads();

        // Rescale accumulators, then O += P V
        float f0 = fRow[(ty << 2) + 0], f1 = fRow[(ty << 2) + 1];
        float f2 = fRow[(ty << 2) + 2], f3 = fRow[(ty << 2) + 3];
        #pragma unroll
        for (int j = 0; j < 4; j++) {
            acc[0][j] *= f0; acc[1][j] *= f1; acc[2][j] *= f2; acc[3][j] *= f3;
        }
        #pragma unroll 8
        for (int j = 0; j < 64; j++) {
            float4 vv = *(const float4*)&Vs[j * 68 + (tx << 2)];
            float p0 = Ss[((ty << 2) + 0) * 68 + j];
            float p1 = Ss[((ty << 2) + 1) * 68 + j];
            float p2 = Ss[((ty << 2) + 2) * 68 + j];
            float p3 = Ss[((ty << 2) + 3) * 68 + j];
            acc[0][0] += p0 * vv.x; acc[0][1] += p0 * vv.y;
            acc[0][2] += p0 * vv.z; acc[0][3] += p0 * vv.w;
            acc[1][0] += p1 * vv.x; acc[1][1] += p1 * vv.y;
            acc[1][2] += p1 * vv.z; acc[1][3] += p1 * vv.w;
            acc[2][0] += p2 * vv.x; acc[2][1] += p2 * vv.y;
            acc[2][2] += p2 * vv.z; acc[2][3] += p2 * vv.w;
            acc[3][0] += p3 * vv.x; acc[3][1] += p3 * vv.y;
            acc[3][2] += p3 * vv.z; acc[3][3] += p3 * vv.w;
        }
    }

    #pragma unroll
    for (int i = 0; i < 4; i++) {
        float inv = 1.0f / sRow[(ty << 2) + i];
        size_t off = (rbase + qt * 64 + (ty << 2) + i) * Dm + h * HSm + (tx << 2);
        float v0 = acc[i][0] * inv, v1 = acc[i][1] * inv;
        float v2 = acc[i][2] * inv, v3 = acc[i][3] * inv;
        __nv_bfloat16 h0, l0, h1, l1, h2, l2, h3, l3;
        split_bf16(v0, h0, l0); split_bf16(v1, h1, l1);
        split_bf16(v2, h2, l2); split_bf16(v3, h3, l3);
        *(__nv_bfloat162*)(Oh + off)     = __halves2bfloat162(h0, h1);
        *(__nv_bfloat162*)(Oh + off + 2) = __halves2bfloat162(h2, h3);
        *(__nv_bfloat162*)(Ol + off)     = __halves2bfloat162(l0, l1);
        *(__nv_bfloat162*)(Ol + off + 2) = __halves2bfloat162(l2, l3);
    }
}

// ---------------------------------------------------------------------------
// Host orchestration (graph-capturable: kernel launches only)
// ---------------------------------------------------------------------------
extern "C" void kernel_launch(void* const* d_in, const int* in_sizes, int n_in,
                              void* d_out, int out_size)
{
    (void)in_sizes; (void)n_in; (void)out_size;
    const int*   x      = (const int*)  d_in[0];
    const float* tok    = (const float*)d_in[1];
    const float* pos    = (const float*)d_in[2];
    const float* wq     = (const float*)d_in[3];
    const float* wk     = (const float*)d_in[4];
    const float* wv     = (const float*)d_in[5];
    const float* w_o    = (const float*)d_in[6];
    const float* b_o    = (const float*)d_in[7];
    const float* ln1_g  = (const float*)d_in[8];
    const float* ln1_b  = (const float*)d_in[9];
    const float* ln2_g  = (const float*)d_in[10];
    const float* ln2_b  = (const float*)d_in[11];
    const float* w1     = (const float*)d_in[12];
    const float* b1     = (const float*)d_in[13];
    const float* w2     = (const float*)d_in[14];
    const float* b2     = (const float*)d_in[15];
    const float* lnf_g  = (const float*)d_in[16];
    const float* lnf_b  = (const float*)d_in[17];
    const float* w_lm   = (const float*)d_in[18];
    const float* b_lm   = (const float*)d_in[19];
    float* out = (float*)d_out;

    float *hb, *hn, *qkvb;
    cudaGetSymbolAddress((void**)&hb, g_h);
    cudaGetSymbolAddress((void**)&hn, g_hn);
    cudaGetSymbolAddress((void**)&qkvb, g_qkv);

    __nv_bfloat16 *ah,*al,*fh,*fl,*wqkvh,*wqkvl,*oh,*ol,*w1h,*w1l,*w2h,*w2l,*lh,*ll;
    cudaGetSymbolAddress((void**)&ah, g_ah);       cudaGetSymbolAddress((void**)&al, g_al);
    cudaGetSymbolAddress((void**)&fh, g_fh);       cudaGetSymbolAddress((void**)&fl, g_fl);
    cudaGetSymbolAddress((void**)&wqkvh, g_wqkvh); cudaGetSymbolAddress((void**)&wqkvl, g_wqkvl);
    cudaGetSymbolAddress((void**)&oh, g_oh);       cudaGetSymbolAddress((void**)&ol, g_ol);
    cudaGetSymbolAddress((void**)&w1h, g_1h);      cudaGetSymbolAddress((void**)&w1l, g_1l);
    cudaGetSymbolAddress((void**)&w2h, g_2h);      cudaGetSymbolAddress((void**)&w2l, g_2l);
    cudaGetSymbolAddress((void**)&lh, g_lh);       cudaGetSymbolAddress((void**)&ll, g_ll);

    cudaFuncSetAttribute(k_attn, cudaFuncAttributeMaxDynamicSharedMemorySize, ATT_SMEM);
    cudaFuncSetAttribute(k_gemm_mma, cudaFuncAttributeMaxDynamicSharedMemorySize, GEMM_SMEM);

    dim3 g1(Dm / 128, Mrows / 128);     // N=1024
    dim3 gq(QKVN / 128, Mrows / 128);   // N=3072
    dim3 g2(FFm / 128, Mrows / 128);    // N=4096
    dim3 gl(Vm / 128, Mrows / 128);     // N=8192
    dim3 ga(Tm / 64, Bm_ * Hm);

    k_embed<<<Mrows, 256>>>(x, tok, pos, hb);

    for (int l = 0; l < Lm; l++) {
        size_t wofs = (size_t)l * Hm * Dm * HSm;
        k_ln<<<Mrows, 256>>>(hb, ln1_g + l * Dm, ln1_b + l * Dm, hn, ah, al);
        k_conv_qkv<<<dim3(16, 16, 3), 256>>>(wq + wofs, wk + wofs, wv + wofs,
                                             wqkvh, wqkvl);
        k_gemm_mma<<<gq, GT, GEMM_SMEM>>>(ah, al, wqkvh, wqkvl, nullptr, nullptr,
                                          qkvb, nullptr, nullptr,
                                          Mrows, QKVN, Dm, 0);
        k_attn<<<ga, 256, ATT_SMEM>>>(qkvb, ah, al);

        k_conv_t<<<dim3(16, 16), 256>>>(w_o + (size_t)l * Dm * Dm, oh, ol, Dm, Dm);
        // h = hn + att @ w_o + b_o
        k_gemm_mma<<<g1, GT, GEMM_SMEM>>>(ah, al, oh, ol, b_o + l * Dm, hn, hb,
                                          nullptr, nullptr, Mrows, Dm, Dm, 0);
        k_ln<<<Mrows, 256>>>(hb, ln2_g + l * Dm, ln2_b + l * Dm, hn, ah, al);

        k_conv_t<<<dim3(64, 16), 256>>>(w1 + (size_t)l * Dm * FFm, w1h, w1l, Dm, FFm);
        // ffn1 = relu(hn @ w1 + b1)  -> split bf16 output directly
        k_gemm_mma<<<g2, GT, GEMM_SMEM>>>(ah, al, w1h, w1l, b1 + l * FFm, nullptr,
                                          nullptr, fh, fl, Mrows, FFm, Dm, 1);
        k_conv_t<<<dim3(16, 64), 256>>>(w2 + (size_t)l * FFm * Dm, w2h, w2l, FFm, Dm);
        // h = hn + ffn1 @ w2 + b2
        k_gemm_mma<<<g1, GT, GEMM_SMEM>>>(fh, fl, w2h, w2l, b2 + l * Dm, hn, hb,
                                          nullptr, nullptr, Mrows, Dm, FFm, 0);
    }

    k_ln<<<Mrows, 256>>>(hb, lnf_g, lnf_b, hn, ah, al);
    k_conv_t<<<dim3(128, 16), 256>>>(w_lm, lh, ll, Dm, Vm);
    k_gemm_mma<<<gl, GT, GEMM_SMEM>>>(ah, al, lh, ll, b_lm, nullptr, out,
                                      nullptr, nullptr, Mrows, Vm, Dm, 0);
}

// round 13
// speedup vs baseline: 1.0484x; 1.0484x over previous
#include <cuda_runtime.h>
#include <cuda_bf16.h>
#include <cstdint>

// ---------------------------------------------------------------------------
// GPT-style transformer forward. GEMMs on tensor cores via mma.sync (bf16x3
// split for fp32-like accuracy); attention fp32 flash-style SIMT.
// B=4, T=1024, D=1024, H=16, HS=64, L=8, FF=4096, V=8192
// ---------------------------------------------------------------------------

#define Dm   1024
#define FFm  4096
#define Vm   8192
#define Hm   16
#define HSm  64
#define Lm   8
#define Bm_  4
#define Tm   1024
#define Mrows (Bm_ * Tm)   // 4096
#define QKVN 3072

// fp32 activation scratch
__device__ float g_h  [Mrows * Dm];
__device__ float g_hn [Mrows * Dm];
__device__ float g_qkv[Mrows * QKVN];

// bf16 split activation scratch
__device__ __nv_bfloat16 g_ah[Mrows * Dm],  g_al[Mrows * Dm];
__device__ __nv_bfloat16 g_fh[Mrows * FFm], g_fl[Mrows * FFm];

// bf16 split weight scratch ([N][K] transposed layout), reused per layer
__device__ __nv_bfloat16 g_wqkvh[QKVN * Dm], g_wqkvl[QKVN * Dm];
__device__ __nv_bfloat16 g_oh[Dm * Dm],  g_ol[Dm * Dm];
__device__ __nv_bfloat16 g_1h[Dm * FFm], g_1l[Dm * FFm];
__device__ __nv_bfloat16 g_2h[Dm * FFm], g_2l[Dm * FFm];
__device__ __nv_bfloat16 g_lh[Dm * Vm],  g_ll[Dm * Vm];

// ---------------------------------------------------------------------------
// helpers
// ---------------------------------------------------------------------------
__device__ __forceinline__ uint32_t smem_u32(const void* p) {
    uint32_t a;
    asm("{ .reg .u64 t; cvta.to.shared.u64 t, %1; cvt.u32.u64 %0, t; }"
        : "=r"(a) : "l"(p));
    return a;
}

__device__ __forceinline__ void split_bf16(float f, __nv_bfloat16& h, __nv_bfloat16& l) {
    h = __float2bfloat16(f);
    l = __float2bfloat16(f - __bfloat162float(h));
}

__device__ __forceinline__ void ldsm4(uint32_t* r, uint32_t addr) {
    asm volatile("ldmatrix.sync.aligned.m8n8.x4.shared.b16 {%0,%1,%2,%3}, [%4];\n"
                 : "=r"(r[0]), "=r"(r[1]), "=r"(r[2]), "=r"(r[3]) : "r"(addr));
}

__device__ __forceinline__ void mma16816(float* c, const uint32_t* a, const uint32_t* b) {
    asm volatile(
        "mma.sync.aligned.m16n8k16.row.col.f32.bf16.bf16.f32 "
        "{%0,%1,%2,%3}, {%4,%5,%6,%7}, {%8,%9}, {%0,%1,%2,%3};\n"
        : "+f"(c[0]), "+f"(c[1]), "+f"(c[2]), "+f"(c[3])
        : "r"(a[0]), "r"(a[1]), "r"(a[2]), "r"(a[3]), "r"(b[0]), "r"(b[1]));
}

// one pass: 4 m16 tiles x 4 n16 tiles (= 32 mma.m16n8k16)
__device__ __forceinline__ void do_pass(float acc[4][8][4],
                                        uint32_t ra[4][4], uint32_t rb[4][4]) {
    #pragma unroll
    for (int i = 0; i < 4; i++)
        #pragma unroll
        for (int j = 0; j < 4; j++) {
            mma16816(acc[i][2 * j + 0], ra[i], &rb[j][0]);
            mma16816(acc[i][2 * j + 1], ra[i], &rb[j][2]);
        }
}

// ---------------------------------------------------------------------------
// Embedding: h[row] = tok_embd[x[row]] + pos_embd[x[row]]   (pos quirk!)
// ---------------------------------------------------------------------------
__global__ void k_embed(const int* __restrict__ x, const float* __restrict__ tok,
                        const float* __restrict__ pos, float* __restrict__ out)
{
    int row = blockIdx.x;
    int t = x[row];
    const float4* te = (const float4*)(tok + (size_t)t * Dm);
    const float4* pe = (const float4*)(pos + (size_t)t * Dm);
    float4* o = (float4*)(out + (size_t)row * Dm);
    int i = threadIdx.x;
    float4 a = te[i], b = pe[i];
    o[i] = make_float4(a.x + b.x, a.y + b.y, a.z + b.z, a.w + b.w);
}

// ---------------------------------------------------------------------------
// LayerNorm over D=1024 + fused bf16 hi/lo split of the output.
// ---------------------------------------------------------------------------
__global__ void k_ln(const float* __restrict__ in, const float* __restrict__ gw,
                     const float* __restrict__ bw, float* __restrict__ out,
                     __nv_bfloat16* __restrict__ oh, __nv_bfloat16* __restrict__ ol)
{
    __shared__ float red[8];
    int row = blockIdx.x;
    int c = threadIdx.x * 4;
    const float* xr = in + (size_t)row * Dm;
    float4 xv = *(const float4*)(xr + c);
    float s = xv.x + xv.y + xv.z + xv.w;
    #pragma unroll
    for (int o = 16; o; o >>= 1) s += __shfl_xor_sync(0xffffffffu, s, o);
    int wid = threadIdx.x >> 5, lid = threadIdx.x & 31;
    if (lid == 0) red[wid] = s;
    __syncthreads();
    float tot = 0.f;
    #pragma unroll
    for (int i = 0; i < 8; i++) tot += red[i];
    float mean = tot * (1.0f / Dm);
    float d0 = xv.x - mean, d1 = xv.y - mean, d2 = xv.z - mean, d3 = xv.w - mean;
    float s2 = d0*d0 + d1*d1 + d2*d2 + d3*d3;
    __syncthreads();
    #pragma unroll
    for (int o = 16; o; o >>= 1) s2 += __shfl_xor_sync(0xffffffffu, s2, o);
    if (lid == 0) red[wid] = s2;
    __syncthreads();
    float v2 = 0.f;
    #pragma unroll
    for (int i = 0; i < 8; i++) v2 += red[i];
    float rstd = rsqrtf(v2 * (1.0f / Dm) + 1e-5f);
    float4 gv = *(const float4*)(gw + c);
    float4 bv = *(const float4*)(bw + c);
    float4 ov = make_float4(d0 * rstd * gv.x + bv.x, d1 * rstd * gv.y + bv.y,
                            d2 * rstd * gv.z + bv.z, d3 * rstd * gv.w + bv.w);
    size_t off = (size_t)row * Dm + c;
    *(float4*)(out + off) = ov;
    __nv_bfloat16 h0, l0, h1, l1, h2, l2, h3, l3;
    split_bf16(ov.x, h0, l0); split_bf16(ov.y, h1, l1);
    split_bf16(ov.z, h2, l2); split_bf16(ov.w, h3, l3);
    *(__nv_bfloat162*)(oh + off)     = __halves2bfloat162(h0, h1);
    *(__nv_bfloat162*)(oh + off + 2) = __halves2bfloat162(h2, h3);
    *(__nv_bfloat162*)(ol + off)     = __halves2bfloat162(l0, l1);
    *(__nv_bfloat162*)(ol + off + 2) = __halves2bfloat162(l2, l3);
}

// ---------------------------------------------------------------------------
// Weight convert: qkv (H,D,HS) -> packed [3072][1024] bf16 hi/lo
// ---------------------------------------------------------------------------
__global__ void k_conv_qkv(const float* __restrict__ wq, const float* __restrict__ wk,
                           const float* __restrict__ wv,
                           __nv_bfloat16* __restrict__ oh,
                           __nv_bfloat16* __restrict__ ol)
{
    __shared__ float t[64][65];
    int h = blockIdx.y;
    int d0 = blockIdx.x << 6;
    int m = blockIdx.z;
    const float* src = (m == 0) ? wq : (m == 1) ? wk : wv;

    const float* base = src + ((size_t)h << 16) + ((size_t)d0 << 6);
    for (int i = threadIdx.x; i < 1024; i += 256) {
        int di = i >> 4, e4 = (i & 15) << 2;
        float4 v = *(const float4*)(base + ((size_t)di << 6) + e4);
        t[di][e4] = v.x; t[di][e4+1] = v.y; t[di][e4+2] = v.z; t[di][e4+3] = v.w;
    }
    __syncthreads();
    for (int i = threadIdx.x; i < 2048; i += 256) {
        int e = i >> 5, d2 = (i & 31) << 1;
        __nv_bfloat16 h0, l0, h1, l1;
        split_bf16(t[d2][e], h0, l0);
        split_bf16(t[d2 + 1][e], h1, l1);
        size_t off = ((size_t)(m * 1024 + h * 64 + e) << 10) + d0 + d2;
        *(__nv_bfloat162*)(oh + off) = __halves2bfloat162(h0, h1);
        *(__nv_bfloat162*)(ol + off) = __halves2bfloat162(l0, l1);
    }
}

// ---------------------------------------------------------------------------
// Weight convert (transpose): in [Kd,Nd] fp32 -> out [Nd][Kd] bf16 hi/lo
// ---------------------------------------------------------------------------
__global__ void k_conv_t(const float* __restrict__ in,
                         __nv_bfloat16* __restrict__ oh,
                         __nv_bfloat16* __restrict__ ol, int Kd, int Nd)
{
    __shared__ float t[64][65];
    int k0 = blockIdx.y << 6, n0 = blockIdx.x << 6;
    for (int i = threadIdx.x; i < 1024; i += 256) {
        int r = i >> 4, c4 = (i & 15) << 2;
        float4 v = *(const float4*)(in + (size_t)(k0 + r) * Nd + n0 + c4);
        t[r][c4] = v.x; t[r][c4+1] = v.y; t[r][c4+2] = v.z; t[r][c4+3] = v.w;
    }
    __syncthreads();
    for (int i = threadIdx.x; i < 2048; i += 256) {
        int n = i >> 5, k2 = (i & 31) << 1;
        __nv_bfloat16 h0, l0, h1, l1;
        split_bf16(t[k2][n], h0, l0);
        split_bf16(t[k2 + 1][n], h1, l1);
        size_t off = (size_t)(n0 + n) * Kd + k0 + k2;
        *(__nv_bfloat162*)(oh + off) = __halves2bfloat162(h0, h1);
        *(__nv_bfloat162*)(ol + off) = __halves2bfloat162(l0, l1);
    }
}

// ---------------------------------------------------------------------------
// Tensor-core GEMM (mma.sync, bf16x3):
// C[M,N] = A[M,K] * B^T  (A as [M][K] hi/lo; B as [N][K] hi/lo)
// 128x128 CTA tile, BK=32, 128 threads (4 warps, 64x64 warp tiles),
// 2-stage cp.async double buffer (SROW=40 -> 80B rows, 16B-aligned,
// conflict-free ldmatrix). Early-prefetch: stage it+2 issued right after the
// last ldmatrix of the iteration, before the final MMA pass.
// ---------------------------------------------------------------------------
#define BK 32
#define SROW 40                       // bf16 elems per smem row (80B)
#define TILE_BYTES (128 * SROW * 2)   // 10240
#define STAGE_BYTES (4 * TILE_BYTES)  // 40960
#define GEMM_SMEM (2 * STAGE_BYTES)   // 81920
#define GT 128                        // gemm threads

__device__ __forceinline__ void issue_stage(
    uint32_t sb, int stage,
    const __nv_bfloat16* Ah, const __nv_bfloat16* Al,
    const __nv_bfloat16* Bh, const __nv_bfloat16* Bl,
    int m0, int n0, int kc, int K, int tid)
{
    uint32_t sbase = sb + stage * STAGE_BYTES;
    #pragma unroll
    for (int i = 0; i < 16; i++) {
        int id = (i << 7) + tid;          // 0..2047
        int tile = id >> 9;               // 0..3 : AH AL BH BL
        int r = (id >> 2) & 127;
        int c = id & 3;                   // 16B chunk within 64B row data
        const __nv_bfloat16* src =
            (tile == 0) ? Ah : (tile == 1) ? Al : (tile == 2) ? Bh : Bl;
        int rowg = ((tile < 2) ? m0 : n0) + r;
        const void* g = src + (size_t)rowg * K + kc + (c << 3);
        uint32_t s = sbase + tile * TILE_BYTES + r * (SROW * 2) + (c << 4);
        asm volatile("cp.async.cg.shared.global [%0], [%1], 16;\n"
                     :: "r"(s), "l"(g));
    }
}

__global__ __launch_bounds__(GT, 2)
void k_gemm_mma(const __nv_bfloat16* __restrict__ Ah, const __nv_bfloat16* __restrict__ Al,
                const __nv_bfloat16* __restrict__ Bh, const __nv_bfloat16* __restrict__ Bl,
                const float* __restrict__ bias, const float* __restrict__ res,
                float* __restrict__ C,
                __nv_bfloat16* __restrict__ Ch, __nv_bfloat16* __restrict__ Cl,
                int M, int N, int K, int relu)
{
    extern __shared__ __align__(128) char sm2[];
    uint32_t sb = smem_u32(sm2);
    int tid = threadIdx.x;
    int lane = tid & 31, wid = tid >> 5;
    int wm = (wid & 1) << 6;    // warp M offset (0/64)
    int wn = (wid >> 1) << 6;   // warp N offset (0/64)
    int m0 = blockIdx.y << 7, n0 = blockIdx.x << 7;

    float acc[4][8][4];
    #pragma unroll
    for (int i = 0; i < 4; i++)
        #pragma unroll
        for (int j = 0; j < 8; j++)
            #pragma unroll
            for (int k = 0; k < 4; k++) acc[i][j][k] = 0.f;

    issue_stage(sb, 0, Ah, Al, Bh, Bl, m0, n0, 0, K, tid);
    asm volatile("cp.async.commit_group;\n" ::: "memory");
    issue_stage(sb, 1, Ah, Al, Bh, Bl, m0, n0, BK, K, tid);
    asm volatile("cp.async.commit_group;\n" ::: "memory");

    // ldmatrix lane address components
    int a_row = ((lane >> 3) & 1) * 8 + (lane & 7);
    int a_k   = (lane >> 4) << 3;
    int b_row = ((lane >> 4) << 3) + (lane & 7);
    int b_k   = ((lane >> 3) & 1) << 3;

    int niter = K / BK;
    for (int it = 0; it < niter; it++) {
        asm volatile("cp.async.wait_group 1;\n" ::: "memory");
        __syncthreads();
        uint32_t st = sb + (it & 1) * STAGE_BYTES;
        uint32_t ra[4][4], rbh[4][4], rbl[4][4];

        // ---- ks = 0 ----
        #pragma unroll
        for (int i = 0; i < 4; i++)
            ldsm4(ra[i], st + ((wm + i * 16 + a_row) * SROW + a_k) * 2);
        #pragma unroll
        for (int j2 = 0; j2 < 4; j2++) {
            uint32_t boff = ((wn + j2 * 16 + b_row) * SROW + b_k) * 2;
            ldsm4(rbh[j2], st + 2 * TILE_BYTES + boff);
            ldsm4(rbl[j2], st + 3 * TILE_BYTES + boff);
        }
        do_pass(acc, ra, rbh);     // Ah*Bh
        do_pass(acc, ra, rbl);     // Ah*Bl
        #pragma unroll
        for (int i = 0; i < 4; i++)
            ldsm4(ra[i], st + TILE_BYTES + ((wm + i * 16 + a_row) * SROW + a_k) * 2);
        do_pass(acc, ra, rbh);     // Al*Bh

        // ---- ks = 1 ----
        #pragma unroll
        for (int i = 0; i < 4; i++)
            ldsm4(ra[i], st + ((wm + i * 16 + a_row) * SROW + 16 + a_k) * 2);
        #pragma unroll
        for (int j2 = 0; j2 < 4; j2++) {
            uint32_t boff = ((wn + j2 * 16 + b_row) * SROW + 16 + b_k) * 2;
            ldsm4(rbh[j2], st + 2 * TILE_BYTES + boff);
            ldsm4(rbl[j2], st + 3 * TILE_BYTES + boff);
        }
        do_pass(acc, ra, rbh);     // Ah*Bh
        do_pass(acc, ra, rbl);     // Ah*Bl
        #pragma unroll
        for (int i = 0; i < 4; i++)
            ldsm4(ra[i], st + TILE_BYTES + ((wm + i * 16 + a_row) * SROW + 16 + a_k) * 2);

        // All shared reads of this stage are now register-complete.
        __syncthreads();
        if (it + 2 < niter)
            issue_stage(sb, it & 1, Ah, Al, Bh, Bl, m0, n0, (it + 2) * BK, K, tid);
        asm volatile("cp.async.commit_group;\n" ::: "memory");

        do_pass(acc, ra, rbh);     // final Al*Bh overlaps with prefetch
    }

    // Epilogue: thread (g,tg) holds rows g,g+8, cols 2*tg..+1 of each m16n8 tile
    int g = lane >> 2, tg = (lane & 3) << 1;
    #pragma unroll
    for (int i = 0; i < 4; i++) {
        int r0 = m0 + wm + i * 16 + g;
        #pragma unroll
        for (int j = 0; j < 8; j++) {
            int col = n0 + wn + j * 8 + tg;
            float v00 = acc[i][j][0], v01 = acc[i][j][1];
            float v10 = acc[i][j][2], v11 = acc[i][j][3];
            if (bias) {
                float2 bb = *(const float2*)(bias + col);
                v00 += bb.x; v01 += bb.y; v10 += bb.x; v11 += bb.y;
            }
            if (relu) {
                v00 = fmaxf(v00, 0.f); v01 = fmaxf(v01, 0.f);
                v10 = fmaxf(v10, 0.f); v11 = fmaxf(v11, 0.f);
            }
            size_t o0 = (size_t)r0 * N + col;
            size_t o1 = o0 + (size_t)8 * N;
            if (Ch) {
                __nv_bfloat16 h0, l0, h1, l1;
                split_bf16(v00, h0, l0); split_bf16(v01, h1, l1);
                *(__nv_bfloat162*)(Ch + o0) = __halves2bfloat162(h0, h1);
                *(__nv_bfloat162*)(Cl + o0) = __halves2bfloat162(l0, l1);
                split_bf16(v10, h0, l0); split_bf16(v11, h1, l1);
                *(__nv_bfloat162*)(Ch + o1) = __halves2bfloat162(h0, h1);
                *(__nv_bfloat162*)(Cl + o1) = __halves2bfloat162(l0, l1);
            } else {
                if (res) {
                    float2 r0v = *(const float2*)(res + o0);
                    float2 r1v = *(const float2*)(res + o1);
                    v00 += r0v.x; v01 += r0v.y; v10 += r1v.x; v11 += r1v.y;
                }
                *(float2*)(C + o0) = make_float2(v00, v01);
                *(float2*)(C + o1) = make_float2(v10, v11);
            }
        }
    }
}

// ---------------------------------------------------------------------------
// Causal attention, flash-style (fp32 SIMT), conflict-aware layout:
// all tiles row-major; S via inner product; softmax 4 threads/row.
// Block = (b, h, 64-query tile). Reads packed qkv [M][3072]; writes bf16 split.
// ---------------------------------------------------------------------------
#define KSTR 65   // K tile row stride (floats), scalar access, 2-way max
#define ATT_SMEM ((3 * 64 * 68 + 64 * KSTR + 192) * 4)

__global__ __launch_bounds__(256)
void k_attn(const float* __restrict__ QKV,
            __nv_bfloat16* __restrict__ Oh, __nv_bfloat16* __restrict__ Ol)
{
    extern __shared__ __align__(16) float smA[];
    float* Qs   = smA;                       // [64][68] row-major, pre-scaled
    float* Vs   = smA + 64 * 68;             // [64][68] row-major
    float* Ss   = smA + 2 * 64 * 68;         // [64][68]
    float* Ks   = smA + 3 * 64 * 68;         // [64][KSTR] row-major (scalar)
    float* mRow = smA + 3 * 64 * 68 + 64 * KSTR;
    float* sRow = mRow + 64;
    float* fRow = sRow + 64;

    int qt = blockIdx.x;
    int bh = blockIdx.y;
    int b = bh >> 4, h = bh & 15;
    int tid = threadIdx.x;
    int tx = tid & 15, ty = tid >> 4;
    size_t rbase = (size_t)b * Tm;
    const float* Q  = QKV + h * HSm;
    const float* Kx = QKV + 1024 + h * HSm;
    const float* Vx = QKV + 2048 + h * HSm;

    for (int i = tid; i < 1024; i += 256) {
        int r = i >> 4, c = (i & 15) << 2;
        float4 qv = *(const float4*)(Q + (rbase + qt * 64 + r) * QKVN + c);
        *(float4*)&Qs[r * 68 + c] = make_float4(qv.x * 0.125f, qv.y * 0.125f,
                                                qv.z * 0.125f, qv.w * 0.125f);
    }
    if (tid < 64) { mRow[tid] = -1e30f; sRow[tid] = 0.f; }

    float acc[4][4] = {};
    int srow = tid >> 2, ssub = tid & 3;     // softmax mapping: 4 thr/row

    for (int kt = 0; kt <= qt; kt++) {
        __syncthreads();   // prev PV done / state visible
        for (int i = tid; i < 1024; i += 256) {
            int r = i >> 4, c = (i & 15) << 2;
            float4 kv = *(const float4*)(Kx + (rbase + kt * 64 + r) * QKVN + c);
            Ks[r * KSTR + c + 0] = kv.x;
            Ks[r * KSTR + c + 1] = kv.y;
            Ks[r * KSTR + c + 2] = kv.z;
            Ks[r * KSTR + c + 3] = kv.w;
            float4 vv = *(const float4*)(Vx + (rbase + kt * 64 + r) * QKVN + c);
            *(float4*)&Vs[r * 68 + c] = vv;
        }
        __syncthreads();

        // S = Q K^T, inner product over e (row-major both sides)
        float sc[4][4] = {};
        #pragma unroll 4
        for (int e = 0; e < 64; e += 4) {
            float4 q0 = *(const float4*)&Qs[((ty << 2) + 0) * 68 + e];
            float4 q1 = *(const float4*)&Qs[((ty << 2) + 1) * 68 + e];
            float4 q2 = *(const float4*)&Qs[((ty << 2) + 2) * 68 + e];
            float4 q3 = *(const float4*)&Qs[((ty << 2) + 3) * 68 + e];
            #pragma unroll
            for (int j = 0; j < 4; j++) {
                const float* kr = &Ks[((tx << 2) + j) * KSTR + e];
                float k0 = kr[0], k1 = kr[1], k2 = kr[2], k3 = kr[3];
                sc[0][j] += q0.x * k0 + q0.y * k1 + q0.z * k2 + q0.w * k3;
                sc[1][j] += q1.x * k0 + q1.y * k1 + q1.z * k2 + q1.w * k3;
                sc[2][j] += q2.x * k0 + q2.y * k1 + q2.z * k2 + q2.w * k3;
                sc[3][j] += q3.x * k0 + q3.y * k1 + q3.z * k2 + q3.w * k3;
            }
        }
        #pragma unroll
        for (int i = 0; i < 4; i++)
            *(float4*)&Ss[((ty << 2) + i) * 68 + (tx << 2)] =
                make_float4(sc[i][0], sc[i][1], sc[i][2], sc[i][3]);
        __syncthreads();

        // Online softmax: 4 threads per row, 16 elems each
        {
            int lim = (kt == qt) ? srow : 63;
            float mOld = mRow[srow];
            float mx = -1e30f;
            #pragma unroll
            for (int t = 0; t < 16; t++) {
                int j = (ssub << 4) + t;
                if (j <= lim) mx = fmaxf(mx, Ss[srow * 68 + j]);
            }
            mx = fmaxf(mx, __shfl_xor_sync(0xffffffffu, mx, 1));
            mx = fmaxf(mx, __shfl_xor_sync(0xffffffffu, mx, 2));
            mx = fmaxf(mx, mOld);
            float sum = 0.f;
            #pragma unroll
            for (int t = 0; t < 16; t++) {
                int j = (ssub << 4) + t;
                float p = (j <= lim) ? __expf(Ss[srow * 68 + j] - mx) : 0.f;
                Ss[srow * 68 + j] = p;
                sum += p;
            }
            sum += __shfl_xor_sync(0xffffffffu, sum, 1);
            sum += __shfl_xor_sync(0xffffffffu, sum, 2);
            if (ssub == 0) {
                float f = __expf(mOld - mx);
                mRow[srow] = mx;
                sRow[srow] = sRow[srow] * f + sum;
                fRow[srow] = f;
            }
        }
        __syncthreads();

        // Rescale accumulators, then O += P V
        float f0 = fRow[(ty << 2) + 0], f1 = fRow[(ty << 2) + 1];
        float f2 = fRow[(ty << 2) + 2], f3 = fRow[(ty << 2) + 3];
        #pragma unroll
        for (int j = 0; j < 4; j++) {
            acc[0][j] *= f0; acc[1][j] *= f1; acc[2][j] *= f2; acc[3][j] *= f3;
        }
        #pragma unroll 8
        for (int j = 0; j < 64; j++) {
            float4 vv = *(const float4*)&Vs[j * 68 + (tx << 2)];
            float p0 = Ss[((ty << 2) + 0) * 68 + j];
            float p1 = Ss[((ty << 2) + 1) * 68 + j];
            float p2 = Ss[((ty << 2) + 2) * 68 + j];
            float p3 = Ss[((ty << 2) + 3) * 68 + j];
            acc[0][0] += p0 * vv.x; acc[0][1] += p0 * vv.y;
            acc[0][2] += p0 * vv.z; acc[0][3] += p0 * vv.w;
            acc[1][0] += p1 * vv.x; acc[1][1] += p1 * vv.y;
            acc[1][2] += p1 * vv.z; acc[1][3] += p1 * vv.w;
            acc[2][0] += p2 * vv.x; acc[2][1] += p2 * vv.y;
            acc[2][2] += p2 * vv.z; acc[2][3] += p2 * vv.w;
            acc[3][0] += p3 * vv.x; acc[3][1] += p3 * vv.y;
            acc[3][2] += p3 * vv.z; acc[3][3] += p3 * vv.w;
        }
    }

    #pragma unroll
    for (int i = 0; i < 4; i++) {
        float inv = 1.0f / sRow[(ty << 2) + i];
        size_t off = (rbase + qt * 64 + (ty << 2) + i) * Dm + h * HSm + (tx << 2);
        float v0 = acc[i][0] * inv, v1 = acc[i][1] * inv;
        float v2 = acc[i][2] * inv, v3 = acc[i][3] * inv;
        __nv_bfloat16 h0, l0, h1, l1, h2, l2, h3, l3;
        split_bf16(v0, h0, l0); split_bf16(v1, h1, l1);
        split_bf16(v2, h2, l2); split_bf16(v3, h3, l3);
        *(__nv_bfloat162*)(Oh + off)     = __halves2bfloat162(h0, h1);
        *(__nv_bfloat162*)(Oh + off + 2) = __halves2bfloat162(h2, h3);
        *(__nv_bfloat162*)(Ol + off)     = __halves2bfloat162(l0, l1);
        *(__nv_bfloat162*)(Ol + off + 2) = __halves2bfloat162(l2, l3);
    }
}

// ---------------------------------------------------------------------------
// Host orchestration (graph-capturable: kernel launches only)
// ---------------------------------------------------------------------------
extern "C" void kernel_launch(void* const* d_in, const int* in_sizes, int n_in,
                              void* d_out, int out_size)
{
    (void)in_sizes; (void)n_in; (void)out_size;
    const int*   x      = (const int*)  d_in[0];
    const float* tok    = (const float*)d_in[1];
    const float* pos    = (const float*)d_in[2];
    const float* wq     = (const float*)d_in[3];
    const float* wk     = (const float*)d_in[4];
    const float* wv     = (const float*)d_in[5];
    const float* w_o    = (const float*)d_in[6];
    const float* b_o    = (const float*)d_in[7];
    const float* ln1_g  = (const float*)d_in[8];
    const float* ln1_b  = (const float*)d_in[9];
    const float* ln2_g  = (const float*)d_in[10];
    const float* ln2_b  = (const float*)d_in[11];
    const float* w1     = (const float*)d_in[12];
    const float* b1     = (const float*)d_in[13];
    const float* w2     = (const float*)d_in[14];
    const float* b2     = (const float*)d_in[15];
    const float* lnf_g  = (const float*)d_in[16];
    const float* lnf_b  = (const float*)d_in[17];
    const float* w_lm   = (const float*)d_in[18];
    const float* b_lm   = (const float*)d_in[19];
    float* out = (float*)d_out;

    float *hb, *hn, *qkvb;
    cudaGetSymbolAddress((void**)&hb, g_h);
    cudaGetSymbolAddress((void**)&hn, g_hn);
    cudaGetSymbolAddress((void**)&qkvb, g_qkv);

    __nv_bfloat16 *ah,*al,*fh,*fl,*wqkvh,*wqkvl,*oh,*ol,*w1h,*w1l,*w2h,*w2l,*lh,*ll;
    cudaGetSymbolAddress((void**)&ah, g_ah);       cudaGetSymbolAddress((void**)&al, g_al);
    cudaGetSymbolAddress((void**)&fh, g_fh);       cudaGetSymbolAddress((void**)&fl, g_fl);
    cudaGetSymbolAddress((void**)&wqkvh, g_wqkvh); cudaGetSymbolAddress((void**)&wqkvl, g_wqkvl);
    cudaGetSymbolAddress((void**)&oh, g_oh);       cudaGetSymbolAddress((void**)&ol, g_ol);
    cudaGetSymbolAddress((void**)&w1h, g_1h);      cudaGetSymbolAddress((void**)&w1l, g_1l);
    cudaGetSymbolAddress((void**)&w2h, g_2h);      cudaGetSymbolAddress((void**)&w2l, g_2l);
    cudaGetSymbolAddress((void**)&lh, g_lh);       cudaGetSymbolAddress((void**)&ll, g_ll);

    cudaFuncSetAttribute(k_attn, cudaFuncAttributeMaxDynamicSharedMemorySize, ATT_SMEM);
    cudaFuncSetAttribute(k_gemm_mma, cudaFuncAttributeMaxDynamicSharedMemorySize, GEMM_SMEM);

    dim3 g1(Dm / 128, Mrows / 128);     // N=1024
    dim3 gq(QKVN / 128, Mrows / 128);   // N=3072
    dim3 g2(FFm / 128, Mrows / 128);    // N=4096
    dim3 gl(Vm / 128, Mrows / 128);     // N=8192
    dim3 ga(Tm / 64, Bm_ * Hm);

    k_embed<<<Mrows, 256>>>(x, tok, pos, hb);

    for (int l = 0; l < Lm; l++) {
        size_t wofs = (size_t)l * Hm * Dm * HSm;
        k_ln<<<Mrows, 256>>>(hb, ln1_g + l * Dm, ln1_b + l * Dm, hn, ah, al);
        k_conv_qkv<<<dim3(16, 16, 3), 256>>>(wq + wofs, wk + wofs, wv + wofs,
                                             wqkvh, wqkvl);
        k_gemm_mma<<<gq, GT, GEMM_SMEM>>>(ah, al, wqkvh, wqkvl, nullptr, nullptr,
                                          qkvb, nullptr, nullptr,
                                          Mrows, QKVN, Dm, 0);
        k_attn<<<ga, 256, ATT_SMEM>>>(qkvb, ah, al);

        k_conv_t<<<dim3(16, 16), 256>>>(w_o + (size_t)l * Dm * Dm, oh, ol, Dm, Dm);
        // h = hn + att @ w_o + b_o
        k_gemm_mma<<<g1, GT, GEMM_SMEM>>>(ah, al, oh, ol, b_o + l * Dm, hn, hb,
                                          nullptr, nullptr, Mrows, Dm, Dm, 0);
        k_ln<<<Mrows, 256>>>(hb, ln2_g + l * Dm, ln2_b + l * Dm, hn, ah, al);

        k_conv_t<<<dim3(64, 16), 256>>>(w1 + (size_t)l * Dm * FFm, w1h, w1l, Dm, FFm);
        // ffn1 = relu(hn @ w1 + b1)  -> split bf16 output directly
        k_gemm_mma<<<g2, GT, GEMM_SMEM>>>(ah, al, w1h, w1l, b1 + l * FFm, nullptr,
                                          nullptr, fh, fl, Mrows, FFm, Dm, 1);
        k_conv_t<<<dim3(16, 64), 256>>>(w2 + (size_t)l * FFm * Dm, w2h, w2l, FFm, Dm);
        // h = hn + ffn1 @ w2 + b2
        k_gemm_mma<<<g1, GT, GEMM_SMEM>>>(fh, fl, w2h, w2l, b2 + l * Dm, hn, hb,
                                          nullptr, nullptr, Mrows, Dm, FFm, 0);
    }

    k_ln<<<Mrows, 256>>>(hb, lnf_g, lnf_b, hn, ah, al);
    k_conv_t<<<dim3(128, 16), 256>>>(w_lm, lh, ll, Dm, Vm);
    k_gemm_mma<<<gl, GT, GEMM_SMEM>>>(ah, al, lh, ll, b_lm, nullptr, out,
                                      nullptr, nullptr, Mrows, Vm, Dm, 0);
}

// round 14
// speedup vs baseline: 1.2976x; 1.2378x over previous
#include <cuda_runtime.h>
#include <cuda_bf16.h>
#include <cstdint>

// ---------------------------------------------------------------------------
// GPT-style transformer forward. GEMMs + attention on tensor cores via
// mma.sync (bf16x3 split for fp32-like accuracy).
// B=4, T=1024, D=1024, H=16, HS=64, L=8, FF=4096, V=8192
// ---------------------------------------------------------------------------

#define Dm   1024
#define FFm  4096
#define Vm   8192
#define Hm   16
#define HSm  64
#define Lm   8
#define Bm_  4
#define Tm   1024
#define Mrows (Bm_ * Tm)   // 4096
#define QKVN 3072

// fp32 activation scratch
__device__ float g_h  [Mrows * Dm];
__device__ float g_hn [Mrows * Dm];

// bf16 split activation scratch
__device__ __nv_bfloat16 g_ah[Mrows * Dm],  g_al[Mrows * Dm];
__device__ __nv_bfloat16 g_fh[Mrows * FFm], g_fl[Mrows * FFm];
__device__ __nv_bfloat16 g_qkvh[Mrows * QKVN], g_qkvl[Mrows * QKVN];

// bf16 split weight scratch ([N][K] transposed layout), reused per layer
__device__ __nv_bfloat16 g_wqkvh[QKVN * Dm], g_wqkvl[QKVN * Dm];
__device__ __nv_bfloat16 g_oh[Dm * Dm],  g_ol[Dm * Dm];
__device__ __nv_bfloat16 g_1h[Dm * FFm], g_1l[Dm * FFm];
__device__ __nv_bfloat16 g_2h[Dm * FFm], g_2l[Dm * FFm];
__device__ __nv_bfloat16 g_lh[Dm * Vm],  g_ll[Dm * Vm];

// ---------------------------------------------------------------------------
// helpers
// ---------------------------------------------------------------------------
__device__ __forceinline__ uint32_t smem_u32(const void* p) {
    uint32_t a;
    asm("{ .reg .u64 t; cvta.to.shared.u64 t, %1; cvt.u32.u64 %0, t; }"
        : "=r"(a) : "l"(p));
    return a;
}

__device__ __forceinline__ void split_bf16(float f, __nv_bfloat16& h, __nv_bfloat16& l) {
    h = __float2bfloat16(f);
    l = __float2bfloat16(f - __bfloat162float(h));
}

__device__ __forceinline__ void ldsm4(uint32_t* r, uint32_t addr) {
    asm volatile("ldmatrix.sync.aligned.m8n8.x4.shared.b16 {%0,%1,%2,%3}, [%4];\n"
                 : "=r"(r[0]), "=r"(r[1]), "=r"(r[2]), "=r"(r[3]) : "r"(addr));
}

__device__ __forceinline__ void ldsm4t(uint32_t* r, uint32_t addr) {
    asm volatile("ldmatrix.sync.aligned.m8n8.x4.trans.shared.b16 {%0,%1,%2,%3}, [%4];\n"
                 : "=r"(r[0]), "=r"(r[1]), "=r"(r[2]), "=r"(r[3]) : "r"(addr));
}

__device__ __forceinline__ void mma16816(float* c, const uint32_t* a, const uint32_t* b) {
    asm volatile(
        "mma.sync.aligned.m16n8k16.row.col.f32.bf16.bf16.f32 "
        "{%0,%1,%2,%3}, {%4,%5,%6,%7}, {%8,%9}, {%0,%1,%2,%3};\n"
        : "+f"(c[0]), "+f"(c[1]), "+f"(c[2]), "+f"(c[3])
        : "r"(a[0]), "r"(a[1]), "r"(a[2]), "r"(a[3]), "r"(b[0]), "r"(b[1]));
}

__device__ __forceinline__ uint32_t packbf2(float a, float b) {
    return (uint32_t)__bfloat16_as_ushort(__float2bfloat16(a)) |
           ((uint32_t)__bfloat16_as_ushort(__float2bfloat16(b)) << 16);
}

// one pass: 4 m16 tiles x 4 n16 tiles (= 32 mma.m16n8k16)
__device__ __forceinline__ void do_pass(float acc[4][8][4],
                                        uint32_t ra[4][4], uint32_t rb[4][4]) {
    #pragma unroll
    for (int i = 0; i < 4; i++)
        #pragma unroll
        for (int j = 0; j < 4; j++) {
            mma16816(acc[i][2 * j + 0], ra[i], &rb[j][0]);
            mma16816(acc[i][2 * j + 1], ra[i], &rb[j][2]);
        }
}

// ---------------------------------------------------------------------------
// Embedding: h[row] = tok_embd[x[row]] + pos_embd[x[row]]   (pos quirk!)
// ---------------------------------------------------------------------------
__global__ void k_embed(const int* __restrict__ x, const float* __restrict__ tok,
                        const float* __restrict__ pos, float* __restrict__ out)
{
    int row = blockIdx.x;
    int t = x[row];
    const float4* te = (const float4*)(tok + (size_t)t * Dm);
    const float4* pe = (const float4*)(pos + (size_t)t * Dm);
    float4* o = (float4*)(out + (size_t)row * Dm);
    int i = threadIdx.x;
    float4 a = te[i], b = pe[i];
    o[i] = make_float4(a.x + b.x, a.y + b.y, a.z + b.z, a.w + b.w);
}

// ---------------------------------------------------------------------------
// LayerNorm over D=1024 + fused bf16 hi/lo split of the output.
// ---------------------------------------------------------------------------
__global__ void k_ln(const float* __restrict__ in, const float* __restrict__ gw,
                     const float* __restrict__ bw, float* __restrict__ out,
                     __nv_bfloat16* __restrict__ oh, __nv_bfloat16* __restrict__ ol)
{
    __shared__ float red[8];
    int row = blockIdx.x;
    int c = threadIdx.x * 4;
    const float* xr = in + (size_t)row * Dm;
    float4 xv = *(const float4*)(xr + c);
    float s = xv.x + xv.y + xv.z + xv.w;
    #pragma unroll
    for (int o = 16; o; o >>= 1) s += __shfl_xor_sync(0xffffffffu, s, o);
    int wid = threadIdx.x >> 5, lid = threadIdx.x & 31;
    if (lid == 0) red[wid] = s;
    __syncthreads();
    float tot = 0.f;
    #pragma unroll
    for (int i = 0; i < 8; i++) tot += red[i];
    float mean = tot * (1.0f / Dm);
    float d0 = xv.x - mean, d1 = xv.y - mean, d2 = xv.z - mean, d3 = xv.w - mean;
    float s2 = d0*d0 + d1*d1 + d2*d2 + d3*d3;
    __syncthreads();
    #pragma unroll
    for (int o = 16; o; o >>= 1) s2 += __shfl_xor_sync(0xffffffffu, s2, o);
    if (lid == 0) red[wid] = s2;
    __syncthreads();
    float v2 = 0.f;
    #pragma unroll
    for (int i = 0; i < 8; i++) v2 += red[i];
    float rstd = rsqrtf(v2 * (1.0f / Dm) + 1e-5f);
    float4 gv = *(const float4*)(gw + c);
    float4 bv = *(const float4*)(bw + c);
    float4 ov = make_float4(d0 * rstd * gv.x + bv.x, d1 * rstd * gv.y + bv.y,
                            d2 * rstd * gv.z + bv.z, d3 * rstd * gv.w + bv.w);
    size_t off = (size_t)row * Dm + c;
    *(float4*)(out + off) = ov;
    __nv_bfloat16 h0, l0, h1, l1, h2, l2, h3, l3;
    split_bf16(ov.x, h0, l0); split_bf16(ov.y, h1, l1);
    split_bf16(ov.z, h2, l2); split_bf16(ov.w, h3, l3);
    *(__nv_bfloat162*)(oh + off)     = __halves2bfloat162(h0, h1);
    *(__nv_bfloat162*)(oh + off + 2) = __halves2bfloat162(h2, h3);
    *(__nv_bfloat162*)(ol + off)     = __halves2bfloat162(l0, l1);
    *(__nv_bfloat162*)(ol + off + 2) = __halves2bfloat162(l2, l3);
}

// ---------------------------------------------------------------------------
// Weight convert: qkv (H,D,HS) -> packed [3072][1024] bf16 hi/lo
// ---------------------------------------------------------------------------
__global__ void k_conv_qkv(const float* __restrict__ wq, const float* __restrict__ wk,
                           const float* __restrict__ wv,
                           __nv_bfloat16* __restrict__ oh,
                           __nv_bfloat16* __restrict__ ol)
{
    __shared__ float t[64][65];
    int h = blockIdx.y;
    int d0 = blockIdx.x << 6;
    int m = blockIdx.z;
    const float* src = (m == 0) ? wq : (m == 1) ? wk : wv;

    const float* base = src + ((size_t)h << 16) + ((size_t)d0 << 6);
    for (int i = threadIdx.x; i < 1024; i += 256) {
        int di = i >> 4, e4 = (i & 15) << 2;
        float4 v = *(const float4*)(base + ((size_t)di << 6) + e4);
        t[di][e4] = v.x; t[di][e4+1] = v.y; t[di][e4+2] = v.z; t[di][e4+3] = v.w;
    }
    __syncthreads();
    for (int i = threadIdx.x; i < 2048; i += 256) {
        int e = i >> 5, d2 = (i & 31) << 1;
        __nv_bfloat16 h0, l0, h1, l1;
        split_bf16(t[d2][e], h0, l0);
        split_bf16(t[d2 + 1][e], h1, l1);
        size_t off = ((size_t)(m * 1024 + h * 64 + e) << 10) + d0 + d2;
        *(__nv_bfloat162*)(oh + off) = __halves2bfloat162(h0, h1);
        *(__nv_bfloat162*)(ol + off) = __halves2bfloat162(l0, l1);
    }
}

// ---------------------------------------------------------------------------
// Weight convert (transpose): in [Kd,Nd] fp32 -> out [Nd][Kd] bf16 hi/lo
// ---------------------------------------------------------------------------
__global__ void k_conv_t(const float* __restrict__ in,
                         __nv_bfloat16* __restrict__ oh,
                         __nv_bfloat16* __restrict__ ol, int Kd, int Nd)
{
    __shared__ float t[64][65];
    int k0 = blockIdx.y << 6, n0 = blockIdx.x << 6;
    for (int i = threadIdx.x; i < 1024; i += 256) {
        int r = i >> 4, c4 = (i & 15) << 2;
        float4 v = *(const float4*)(in + (size_t)(k0 + r) * Nd + n0 + c4);
        t[r][c4] = v.x; t[r][c4+1] = v.y; t[r][c4+2] = v.z; t[r][c4+3] = v.w;
    }
    __syncthreads();
    for (int i = threadIdx.x; i < 2048; i += 256) {
        int n = i >> 5, k2 = (i & 31) << 1;
        __nv_bfloat16 h0, l0, h1, l1;
        split_bf16(t[k2][n], h0, l0);
        split_bf16(t[k2 + 1][n], h1, l1);
        size_t off = (size_t)(n0 + n) * Kd + k0 + k2;
        *(__nv_bfloat162*)(oh + off) = __halves2bfloat162(h0, h1);
        *(__nv_bfloat162*)(ol + off) = __halves2bfloat162(l0, l1);
    }
}

// ---------------------------------------------------------------------------
// Tensor-core GEMM (mma.sync, bf16x3) — unchanged from best measured config.
// ---------------------------------------------------------------------------
#define BK 32
#define SROW 40                       // bf16 elems per smem row (80B)
#define TILE_BYTES (128 * SROW * 2)   // 10240
#define STAGE_BYTES (4 * TILE_BYTES)  // 40960
#define GEMM_SMEM (2 * STAGE_BYTES)   // 81920
#define GT 128                        // gemm threads

__device__ __forceinline__ void issue_stage(
    uint32_t sb, int stage,
    const __nv_bfloat16* Ah, const __nv_bfloat16* Al,
    const __nv_bfloat16* Bh, const __nv_bfloat16* Bl,
    int m0, int n0, int kc, int K, int tid)
{
    uint32_t sbase = sb + stage * STAGE_BYTES;
    #pragma unroll
    for (int i = 0; i < 16; i++) {
        int id = (i << 7) + tid;          // 0..2047
        int tile = id >> 9;               // 0..3 : AH AL BH BL
        int r = (id >> 2) & 127;
        int c = id & 3;                   // 16B chunk within 64B row data
        const __nv_bfloat16* src =
            (tile == 0) ? Ah : (tile == 1) ? Al : (tile == 2) ? Bh : Bl;
        int rowg = ((tile < 2) ? m0 : n0) + r;
        const void* g = src + (size_t)rowg * K + kc + (c << 3);
        uint32_t s = sbase + tile * TILE_BYTES + r * (SROW * 2) + (c << 4);
        asm volatile("cp.async.cg.shared.global [%0], [%1], 16;\n"
                     :: "r"(s), "l"(g));
    }
}

__global__ __launch_bounds__(GT, 2)
void k_gemm_mma(const __nv_bfloat16* __restrict__ Ah, const __nv_bfloat16* __restrict__ Al,
                const __nv_bfloat16* __restrict__ Bh, const __nv_bfloat16* __restrict__ Bl,
                const float* __restrict__ bias, const float* __restrict__ res,
                float* __restrict__ C,
                __nv_bfloat16* __restrict__ Ch, __nv_bfloat16* __restrict__ Cl,
                int M, int N, int K, int relu)
{
    extern __shared__ __align__(128) char sm2[];
    uint32_t sb = smem_u32(sm2);
    int tid = threadIdx.x;
    int lane = tid & 31, wid = tid >> 5;
    int wm = (wid & 1) << 6;
    int wn = (wid >> 1) << 6;
    int m0 = blockIdx.y << 7, n0 = blockIdx.x << 7;

    float acc[4][8][4];
    #pragma unroll
    for (int i = 0; i < 4; i++)
        #pragma unroll
        for (int j = 0; j < 8; j++)
            #pragma unroll
            for (int k = 0; k < 4; k++) acc[i][j][k] = 0.f;

    issue_stage(sb, 0, Ah, Al, Bh, Bl, m0, n0, 0, K, tid);
    asm volatile("cp.async.commit_group;\n" ::: "memory");
    issue_stage(sb, 1, Ah, Al, Bh, Bl, m0, n0, BK, K, tid);
    asm volatile("cp.async.commit_group;\n" ::: "memory");

    int a_row = ((lane >> 3) & 1) * 8 + (lane & 7);
    int a_k   = (lane >> 4) << 3;
    int b_row = ((lane >> 4) << 3) + (lane & 7);
    int b_k   = ((lane >> 3) & 1) << 3;

    int niter = K / BK;
    for (int it = 0; it < niter; it++) {
        asm volatile("cp.async.wait_group 1;\n" ::: "memory");
        __syncthreads();
        uint32_t st = sb + (it & 1) * STAGE_BYTES;
        uint32_t ra[4][4], rbh[4][4], rbl[4][4];

        // ---- ks = 0 ----
        #pragma unroll
        for (int i = 0; i < 4; i++)
            ldsm4(ra[i], st + ((wm + i * 16 + a_row) * SROW + a_k) * 2);
        #pragma unroll
        for (int j2 = 0; j2 < 4; j2++) {
            uint32_t boff = ((wn + j2 * 16 + b_row) * SROW + b_k) * 2;
            ldsm4(rbh[j2], st + 2 * TILE_BYTES + boff);
            ldsm4(rbl[j2], st + 3 * TILE_BYTES + boff);
        }
        do_pass(acc, ra, rbh);
        do_pass(acc, ra, rbl);
        #pragma unroll
        for (int i = 0; i < 4; i++)
            ldsm4(ra[i], st + TILE_BYTES + ((wm + i * 16 + a_row) * SROW + a_k) * 2);
        do_pass(acc, ra, rbh);

        // ---- ks = 1 ----
        #pragma unroll
        for (int i = 0; i < 4; i++)
            ldsm4(ra[i], st + ((wm + i * 16 + a_row) * SROW + 16 + a_k) * 2);
        #pragma unroll
        for (int j2 = 0; j2 < 4; j2++) {
            uint32_t boff = ((wn + j2 * 16 + b_row) * SROW + 16 + b_k) * 2;
            ldsm4(rbh[j2], st + 2 * TILE_BYTES + boff);
            ldsm4(rbl[j2], st + 3 * TILE_BYTES + boff);
        }
        do_pass(acc, ra, rbh);
        do_pass(acc, ra, rbl);
        #pragma unroll
        for (int i = 0; i < 4; i++)
            ldsm4(ra[i], st + TILE_BYTES + ((wm + i * 16 + a_row) * SROW + 16 + a_k) * 2);

        __syncthreads();
        if (it + 2 < niter)
            issue_stage(sb, it & 1, Ah, Al, Bh, Bl, m0, n0, (it + 2) * BK, K, tid);
        asm volatile("cp.async.commit_group;\n" ::: "memory");

        do_pass(acc, ra, rbh);
    }

    int g = lane >> 2, tg = (lane & 3) << 1;
    #pragma unroll
    for (int i = 0; i < 4; i++) {
        int r0 = m0 + wm + i * 16 + g;
        #pragma unroll
        for (int j = 0; j < 8; j++) {
            int col = n0 + wn + j * 8 + tg;
            float v00 = acc[i][j][0], v01 = acc[i][j][1];
            float v10 = acc[i][j][2], v11 = acc[i][j][3];
            if (bias) {
                float2 bb = *(const float2*)(bias + col);
                v00 += bb.x; v01 += bb.y; v10 += bb.x; v11 += bb.y;
            }
            if (relu) {
                v00 = fmaxf(v00, 0.f); v01 = fmaxf(v01, 0.f);
                v10 = fmaxf(v10, 0.f); v11 = fmaxf(v11, 0.f);
            }
            size_t o0 = (size_t)r0 * N + col;
            size_t o1 = o0 + (size_t)8 * N;
            if (Ch) {
                __nv_bfloat16 h0, l0, h1, l1;
                split_bf16(v00, h0, l0); split_bf16(v01, h1, l1);
                *(__nv_bfloat162*)(Ch + o0) = __halves2bfloat162(h0, h1);
                *(__nv_bfloat162*)(Cl + o0) = __halves2bfloat162(l0, l1);
                split_bf16(v10, h0, l0); split_bf16(v11, h1, l1);
                *(__nv_bfloat162*)(Ch + o1) = __halves2bfloat162(h0, h1);
                *(__nv_bfloat162*)(Cl + o1) = __halves2bfloat162(l0, l1);
            } else {
                if (res) {
                    float2 r0v = *(const float2*)(res + o0);
                    float2 r1v = *(const float2*)(res + o1);
                    v00 += r0v.x; v01 += r0v.y; v10 += r1v.x; v11 += r1v.y;
                }
                *(float2*)(C + o0) = make_float2(v00, v01);
                *(float2*)(C + o1) = make_float2(v10, v11);
            }
        }
    }
}

// ---------------------------------------------------------------------------
// Tensor-core causal attention (bf16x3, flash-style, FA2 register softmax).
// Block = (qt, b*16+h), 128 threads / 4 warps; warp owns 16 query rows.
// Reads split-bf16 packed qkv [M][3072]; writes split-bf16 output [M][1024].
// ---------------------------------------------------------------------------
#define ASROW 72                      // bf16 per smem row (144B, conflict-free)
#define ATILE (64 * ASROW * 2)        // 9216 B per tile
#define ATT_SMEM (6 * ATILE)          // Qh Ql Kh Kl Vh Vl = 55296 B

__global__ __launch_bounds__(128)
void k_attn_tc(const __nv_bfloat16* __restrict__ Xh,
               const __nv_bfloat16* __restrict__ Xl,
               __nv_bfloat16* __restrict__ Oh, __nv_bfloat16* __restrict__ Ol)
{
    extern __shared__ __align__(128) char smA[];
    uint32_t sb = smem_u32(smA);
    const uint32_t sQH = sb, sQL = sb + ATILE, sKH = sb + 2 * ATILE,
                   sKL = sb + 3 * ATILE, sVH = sb + 4 * ATILE, sVL = sb + 5 * ATILE;

    int qt = blockIdx.x, bh = blockIdx.y;
    int b = bh >> 4, h = bh & 15;
    int tid = threadIdx.x, lane = tid & 31, w = tid >> 5;
    size_t rbase = (size_t)b * Tm;
    int colQ = h * HSm, colK = 1024 + h * HSm, colV = 2048 + h * HSm;

    // ---- load Q tiles (hi/lo) ----
    #pragma unroll
    for (int i = 0; i < 8; i++) {
        int id = (i << 7) + tid;          // 0..1023
        int tile = id >> 9;               // 0:Qh 1:Ql
        int r = (id >> 3) & 63, c = id & 7;
        const __nv_bfloat16* src = (tile == 0) ? Xh : Xl;
        const void* g = src + (rbase + qt * 64 + r) * QKVN + colQ + (c << 3);
        uint32_t s = (tile == 0 ? sQH : sQL) + r * (ASROW * 2) + (c << 4);
        asm volatile("cp.async.cg.shared.global [%0], [%1], 16;\n" :: "r"(s), "l"(g));
    }
    asm volatile("cp.async.commit_group;\n" ::: "memory");
    asm volatile("cp.async.wait_group 0;\n" ::: "memory");
    __syncthreads();

    // ---- cache Q fragments in registers (loop-invariant) ----
    int a_row = ((lane >> 3) & 1) * 8 + (lane & 7);
    int a_k   = (lane >> 4) << 3;
    uint32_t aqh[4][4], aql[4][4];
    #pragma unroll
    for (int ks = 0; ks < 4; ks++) {
        uint32_t off = ((w * 16 + a_row) * ASROW + ks * 16 + a_k) * 2;
        ldsm4(aqh[ks], sQH + off);
        ldsm4(aql[ks], sQL + off);
    }

    float o[8][4];
    #pragma unroll
    for (int j = 0; j < 8; j++)
        #pragma unroll
        for (int c = 0; c < 4; c++) o[j][c] = 0.f;
    float m0r = -1e30f, m1r = -1e30f, s0r = 0.f, s1r = 0.f;

    int g = lane >> 2, tg = lane & 3;
    int row0 = w * 16 + g, row1 = row0 + 8;      // rows within q-tile
    int b_row = ((lane >> 4) << 3) + (lane & 7); // K frag (non-trans B)
    int b_k   = ((lane >> 3) & 1) << 3;
    int t_row = lane & 15;                       // V frag (trans B)
    int t_col = (lane >> 4) << 3;

    for (int kt = 0; kt <= qt; kt++) {
        __syncthreads();   // previous iteration's smem reads complete
        #pragma unroll
        for (int i = 0; i < 16; i++) {
            int id = (i << 7) + tid;          // 0..2047
            int tile = id >> 9;               // 0:Kh 1:Kl 2:Vh 3:Vl
            int r = (id >> 3) & 63, c = id & 7;
            const __nv_bfloat16* src = (tile == 0 || tile == 2) ? Xh : Xl;
            int colb = (tile < 2) ? colK : colV;
            const void* gp = src + (rbase + kt * 64 + r) * QKVN + colb + (c << 3);
            uint32_t s = sKH + tile * ATILE + r * (ASROW * 2) + (c << 4);
            asm volatile("cp.async.cg.shared.global [%0], [%1], 16;\n" :: "r"(s), "l"(gp));
        }
        asm volatile("cp.async.commit_group;\n" ::: "memory");
        asm volatile("cp.async.wait_group 0;\n" ::: "memory");
        __syncthreads();

        // ---- S = Q K^T (bf16x3) ----
        float s[8][4];
        #pragma unroll
        for (int j = 0; j < 8; j++)
            #pragma unroll
            for (int c = 0; c < 4; c++) s[j][c] = 0.f;
        #pragma unroll
        for (int ks = 0; ks < 4; ks++) {
            uint32_t kh[4][4], kl[4][4];
            #pragma unroll
            for (int j2 = 0; j2 < 4; j2++) {
                uint32_t boff = ((j2 * 16 + b_row) * ASROW + ks * 16 + b_k) * 2;
                ldsm4(kh[j2], sKH + boff);
                ldsm4(kl[j2], sKL + boff);
            }
            #pragma unroll
            for (int j2 = 0; j2 < 4; j2++) {
                mma16816(s[2 * j2 + 0], aqh[ks], &kh[j2][0]);
                mma16816(s[2 * j2 + 1], aqh[ks], &kh[j2][2]);
            }
            #pragma unroll
            for (int j2 = 0; j2 < 4; j2++) {
                mma16816(s[2 * j2 + 0], aqh[ks], &kl[j2][0]);
                mma16816(s[2 * j2 + 1], aqh[ks], &kl[j2][2]);
            }
            #pragma unroll
            for (int j2 = 0; j2 < 4; j2++) {
                mma16816(s[2 * j2 + 0], aql[ks], &kh[j2][0]);
                mma16816(s[2 * j2 + 1], aql[ks], &kh[j2][2]);
            }
        }
        // scale + causal mask (diag tile only)
        #pragma unroll
        for (int j = 0; j < 8; j++)
            #pragma unroll
            for (int c = 0; c < 4; c++) s[j][c] *= 0.125f;
        if (kt == qt) {
            #pragma unroll
            for (int j = 0; j < 8; j++) {
                int c0 = 8 * j + 2 * tg, c1 = c0 + 1;
                if (c0 > row0) s[j][0] = -1e30f;
                if (c1 > row0) s[j][1] = -1e30f;
                if (c0 > row1) s[j][2] = -1e30f;
                if (c1 > row1) s[j][3] = -1e30f;
            }
        }
        // ---- online softmax on register fragments ----
        float mx0 = -1e30f, mx1 = -1e30f;
        #pragma unroll
        for (int j = 0; j < 8; j++) {
            mx0 = fmaxf(mx0, fmaxf(s[j][0], s[j][1]));
            mx1 = fmaxf(mx1, fmaxf(s[j][2], s[j][3]));
        }
        mx0 = fmaxf(mx0, __shfl_xor_sync(0xffffffffu, mx0, 1));
        mx0 = fmaxf(mx0, __shfl_xor_sync(0xffffffffu, mx0, 2));
        mx1 = fmaxf(mx1, __shfl_xor_sync(0xffffffffu, mx1, 1));
        mx1 = fmaxf(mx1, __shfl_xor_sync(0xffffffffu, mx1, 2));
        mx0 = fmaxf(mx0, m0r); mx1 = fmaxf(mx1, m1r);
        float f0 = __expf(m0r - mx0), f1 = __expf(m1r - mx1);
        m0r = mx0; m1r = mx1;
        float sum0 = 0.f, sum1 = 0.f;
        #pragma unroll
        for (int j = 0; j < 8; j++) {
            s[j][0] = __expf(s[j][0] - mx0); sum0 += s[j][0];
            s[j][1] = __expf(s[j][1] - mx0); sum0 += s[j][1];
            s[j][2] = __expf(s[j][2] - mx1); sum1 += s[j][2];
            s[j][3] = __expf(s[j][3] - mx1); sum1 += s[j][3];
        }
        sum0 += __shfl_xor_sync(0xffffffffu, sum0, 1);
        sum0 += __shfl_xor_sync(0xffffffffu, sum0, 2);
        sum1 += __shfl_xor_sync(0xffffffffu, sum1, 1);
        sum1 += __shfl_xor_sync(0xffffffffu, sum1, 2);
        s0r = s0r * f0 + sum0;
        s1r = s1r * f1 + sum1;
        #pragma unroll
        for (int j = 0; j < 8; j++) {
            o[j][0] *= f0; o[j][1] *= f0; o[j][2] *= f1; o[j][3] *= f1;
        }
        // ---- O += P V (bf16x3), P from S fragments (FA2 layout identity) ----
        #pragma unroll
        for (int ks = 0; ks < 4; ks++) {
            uint32_t ph[4], pl[4];
            {
                float p00 = s[2 * ks][0], p01 = s[2 * ks][1];
                float p10 = s[2 * ks][2], p11 = s[2 * ks][3];
                float q00 = s[2 * ks + 1][0], q01 = s[2 * ks + 1][1];
                float q10 = s[2 * ks + 1][2], q11 = s[2 * ks + 1][3];
                ph[0] = packbf2(p00, p01);
                ph[1] = packbf2(p10, p11);
                ph[2] = packbf2(q00, q01);
                ph[3] = packbf2(q10, q11);
                pl[0] = packbf2(p00 - __bfloat162float(__float2bfloat16(p00)),
                                p01 - __bfloat162float(__float2bfloat16(p01)));
                pl[1] = packbf2(p10 - __bfloat162float(__float2bfloat16(p10)),
                                p11 - __bfloat162float(__float2bfloat16(p11)));
                pl[2] = packbf2(q00 - __bfloat162float(__float2bfloat16(q00)),
                                q01 - __bfloat162float(__float2bfloat16(q01)));
                pl[3] = packbf2(q10 - __bfloat162float(__float2bfloat16(q10)),
                                q11 - __bfloat162float(__float2bfloat16(q11)));
            }
            uint32_t vh[4][4], vl[4][4];
            #pragma unroll
            for (int j2 = 0; j2 < 4; j2++) {
                uint32_t voff = ((ks * 16 + t_row) * ASROW + j2 * 16 + t_col) * 2;
                ldsm4t(vh[j2], sVH + voff);
                ldsm4t(vl[j2], sVL + voff);
            }
            #pragma unroll
            for (int j2 = 0; j2 < 4; j2++) {
                mma16816(o[2 * j2 + 0], ph, &vh[j2][0]);
                mma16816(o[2 * j2 + 1], ph, &vh[j2][2]);
            }
            #pragma unroll
            for (int j2 = 0; j2 < 4; j2++) {
                mma16816(o[2 * j2 + 0], ph, &vl[j2][0]);
                mma16816(o[2 * j2 + 1], ph, &vl[j2][2]);
            }
            #pragma unroll
            for (int j2 = 0; j2 < 4; j2++) {
                mma16816(o[2 * j2 + 0], pl, &vh[j2][0]);
                mma16816(o[2 * j2 + 1], pl, &vh[j2][2]);
            }
        }
    }

    // ---- epilogue: O / s, write split bf16 ----
    float inv0 = 1.0f / s0r, inv1 = 1.0f / s1r;
    size_t rg0 = (rbase + qt * 64 + row0) * Dm;
    size_t rg1 = (rbase + qt * 64 + row1) * Dm;
    #pragma unroll
    for (int j = 0; j < 8; j++) {
        int col = h * HSm + 8 * j + 2 * tg;
        float v00 = o[j][0] * inv0, v01 = o[j][1] * inv0;
        float v10 = o[j][2] * inv1, v11 = o[j][3] * inv1;
        __nv_bfloat16 h0, l0, h1, l1;
        split_bf16(v00, h0, l0); split_bf16(v01, h1, l1);
        *(__nv_bfloat162*)(Oh + rg0 + col) = __halves2bfloat162(h0, h1);
        *(__nv_bfloat162*)(Ol + rg0 + col) = __halves2bfloat162(l0, l1);
        split_bf16(v10, h0, l0); split_bf16(v11, h1, l1);
        *(__nv_bfloat162*)(Oh + rg1 + col) = __halves2bfloat162(h0, h1);
        *(__nv_bfloat162*)(Ol + rg1 + col) = __halves2bfloat162(l0, l1);
    }
}

// ---------------------------------------------------------------------------
// Host orchestration (graph-capturable: kernel launches only)
// ---------------------------------------------------------------------------
extern "C" void kernel_launch(void* const* d_in, const int* in_sizes, int n_in,
                              void* d_out, int out_size)
{
    (void)in_sizes; (void)n_in; (void)out_size;
    const int*   x      = (const int*)  d_in[0];
    const float* tok    = (const float*)d_in[1];
    const float* pos    = (const float*)d_in[2];
    const float* wq     = (const float*)d_in[3];
    const float* wk     = (const float*)d_in[4];
    const float* wv     = (const float*)d_in[5];
    const float* w_o    = (const float*)d_in[6];
    const float* b_o    = (const float*)d_in[7];
    const float* ln1_g  = (const float*)d_in[8];
    const float* ln1_b  = (const float*)d_in[9];
    const float* ln2_g  = (const float*)d_in[10];
    const float* ln2_b  = (const float*)d_in[11];
    const float* w1     = (const float*)d_in[12];
    const float* b1     = (const float*)d_in[13];
    const float* w2     = (const float*)d_in[14];
    const float* b2     = (const float*)d_in[15];
    const float* lnf_g  = (const float*)d_in[16];
    const float* lnf_b  = (const float*)d_in[17];
    const float* w_lm   = (const float*)d_in[18];
    const float* b_lm   = (const float*)d_in[19];
    float* out = (float*)d_out;

    float *hb, *hn;
    cudaGetSymbolAddress((void**)&hb, g_h);
    cudaGetSymbolAddress((void**)&hn, g_hn);

    __nv_bfloat16 *ah,*al,*fh,*fl,*qkvh,*qkvl,*wqkvh,*wqkvl,*oh,*ol,
                  *w1h,*w1l,*w2h,*w2l,*lh,*ll;
    cudaGetSymbolAddress((void**)&ah, g_ah);       cudaGetSymbolAddress((void**)&al, g_al);
    cudaGetSymbolAddress((void**)&fh, g_fh);       cudaGetSymbolAddress((void**)&fl, g_fl);
    cudaGetSymbolAddress((void**)&qkvh, g_qkvh);   cudaGetSymbolAddress((void**)&qkvl, g_qkvl);
    cudaGetSymbolAddress((void**)&wqkvh, g_wqkvh); cudaGetSymbolAddress((void**)&wqkvl, g_wqkvl);
    cudaGetSymbolAddress((void**)&oh, g_oh);       cudaGetSymbolAddress((void**)&ol, g_ol);
    cudaGetSymbolAddress((void**)&w1h, g_1h);      cudaGetSymbolAddress((void**)&w1l, g_1l);
    cudaGetSymbolAddress((void**)&w2h, g_2h);      cudaGetSymbolAddress((void**)&w2l, g_2l);
    cudaGetSymbolAddress((void**)&lh, g_lh);       cudaGetSymbolAddress((void**)&ll, g_ll);

    cudaFuncSetAttribute(k_attn_tc, cudaFuncAttributeMaxDynamicSharedMemorySize, ATT_SMEM);
    cudaFuncSetAttribute(k_gemm_mma, cudaFuncAttributeMaxDynamicSharedMemorySize, GEMM_SMEM);

    dim3 g1(Dm / 128, Mrows / 128);     // N=1024
    dim3 gq(QKVN / 128, Mrows / 128);   // N=3072
    dim3 g2(FFm / 128, Mrows / 128);    // N=4096
    dim3 gl(Vm / 128, Mrows / 128);     // N=8192
    dim3 ga(Tm / 64, Bm_ * Hm);

    k_embed<<<Mrows, 256>>>(x, tok, pos, hb);

    for (int l = 0; l < Lm; l++) {
        size_t wofs = (size_t)l * Hm * Dm * HSm;
        k_ln<<<Mrows, 256>>>(hb, ln1_g + l * Dm, ln1_b + l * Dm, hn, ah, al);
        k_conv_qkv<<<dim3(16, 16, 3), 256>>>(wq + wofs, wk + wofs, wv + wofs,
                                             wqkvh, wqkvl);
        // qkv (split bf16 output)
        k_gemm_mma<<<gq, GT, GEMM_SMEM>>>(ah, al, wqkvh, wqkvl, nullptr, nullptr,
                                          nullptr, qkvh, qkvl, Mrows, QKVN, Dm, 0);
        k_attn_tc<<<ga, 128, ATT_SMEM>>>(qkvh, qkvl, ah, al);

        k_conv_t<<<dim3(16, 16), 256>>>(w_o + (size_t)l * Dm * Dm, oh, ol, Dm, Dm);
        // h = hn + att @ w_o + b_o
        k_gemm_mma<<<g1, GT, GEMM_SMEM>>>(ah, al, oh, ol, b_o + l * Dm, hn, hb,
                                          nullptr, nullptr, Mrows, Dm, Dm, 0);
        k_ln<<<Mrows, 256>>>(hb, ln2_g + l * Dm, ln2_b + l * Dm, hn, ah, al);

        k_conv_t<<<dim3(64, 16), 256>>>(w1 + (size_t)l * Dm * FFm, w1h, w1l, Dm, FFm);
        // ffn1 = relu(hn @ w1 + b1)  -> split bf16 output directly
        k_gemm_mma<<<g2, GT, GEMM_SMEM>>>(ah, al, w1h, w1l, b1 + l * FFm, nullptr,
                                          nullptr, fh, fl, Mrows, FFm, Dm, 1);
        k_conv_t<<<dim3(16, 64), 256>>>(w2 + (size_t)l * FFm * Dm, w2h, w2l, FFm, Dm);
        // h = hn + ffn1 @ w2 + b2
        k_gemm_mma<<<g1, GT, GEMM_SMEM>>>(fh, fl, w2h, w2l, b2 + l * Dm, hn, hb,
                                          nullptr, nullptr, Mrows, Dm, FFm, 0);
    }

    k_ln<<<Mrows, 256>>>(hb, lnf_g, lnf_b, hn, ah, al);
    k_conv_t<<<dim3(128, 16), 256>>>(w_lm, lh, ll, Dm, Vm);
    k_gemm_mma<<<gl, GT, GEMM_SMEM>>>(ah, al, lh, ll, b_lm, nullptr, out,
                                      nullptr, nullptr, Mrows, Vm, Dm, 0);
}

// round 15
// speedup vs baseline: 1.9690x; 1.5174x over previous
#include <cuda_runtime.h>
#include <cuda_fp16.h>
#include <cstdint>

// ---------------------------------------------------------------------------
// GPT-style transformer forward. GEMMs + attention on tensor cores via
// mma.sync fp16: C = Ah*(Bh+Bl), A quantized to fp16, B split to ~22 bits.
// B=4, T=1024, D=1024, H=16, HS=64, L=8, FF=4096, V=8192
// ---------------------------------------------------------------------------

#define Dm   1024
#define FFm  4096
#define Vm   8192
#define Hm   16
#define HSm  64
#define Lm   8
#define Bm_  4
#define Tm   1024
#define Mrows (Bm_ * Tm)   // 4096
#define QKVN 3072

// fp32 activation scratch
__device__ float g_h  [Mrows * Dm];
__device__ float g_hn [Mrows * Dm];

// fp16 activation scratch
__device__ __half g_ah[Mrows * Dm];            // LN out / attn out (hi only)
__device__ __half g_fh[Mrows * FFm];           // FFN1 out (hi only)
__device__ __half g_qkvh[Mrows * QKVN], g_qkvl[Mrows * QKVN];

// fp16 split weight scratch ([N][K] transposed layout), reused per layer
__device__ __half g_wqkvh[QKVN * Dm], g_wqkvl[QKVN * Dm];
__device__ __half g_oh[Dm * Dm],  g_ol[Dm * Dm];
__device__ __half g_1h[Dm * FFm], g_1l[Dm * FFm];
__device__ __half g_2h[Dm * FFm], g_2l[Dm * FFm];
__device__ __half g_lh[Dm * Vm],  g_ll[Dm * Vm];

// ---------------------------------------------------------------------------
// helpers
// ---------------------------------------------------------------------------
__device__ __forceinline__ uint32_t smem_u32(const void* p) {
    uint32_t a;
    asm("{ .reg .u64 t; cvta.to.shared.u64 t, %1; cvt.u32.u64 %0, t; }"
        : "=r"(a) : "l"(p));
    return a;
}

__device__ __forceinline__ void split_f16(float f, __half& h, __half& l) {
    h = __float2half_rn(f);
    l = __float2half_rn(f - __half2float(h));
}
__device__ __forceinline__ uint32_t pack_h2(__half a, __half b) {
    return (uint32_t)__half_as_ushort(a) | ((uint32_t)__half_as_ushort(b) << 16);
}
__device__ __forceinline__ uint32_t packf_h2(float a, float b) {
    return pack_h2(__float2half_rn(a), __float2half_rn(b));
}

__device__ __forceinline__ void ldsm4(uint32_t* r, uint32_t addr) {
    asm volatile("ldmatrix.sync.aligned.m8n8.x4.shared.b16 {%0,%1,%2,%3}, [%4];\n"
                 : "=r"(r[0]), "=r"(r[1]), "=r"(r[2]), "=r"(r[3]) : "r"(addr));
}
__device__ __forceinline__ void ldsm4t(uint32_t* r, uint32_t addr) {
    asm volatile("ldmatrix.sync.aligned.m8n8.x4.trans.shared.b16 {%0,%1,%2,%3}, [%4];\n"
                 : "=r"(r[0]), "=r"(r[1]), "=r"(r[2]), "=r"(r[3]) : "r"(addr));
}

__device__ __forceinline__ void mma16816(float* c, const uint32_t* a, const uint32_t* b) {
    asm volatile(
        "mma.sync.aligned.m16n8k16.row.col.f32.f16.f16.f32 "
        "{%0,%1,%2,%3}, {%4,%5,%6,%7}, {%8,%9}, {%0,%1,%2,%3};\n"
        : "+f"(c[0]), "+f"(c[1]), "+f"(c[2]), "+f"(c[3])
        : "r"(a[0]), "r"(a[1]), "r"(a[2]), "r"(a[3]), "r"(b[0]), "r"(b[1]));
}

// one pass: 4 m16 tiles x 4 n16 tiles (= 32 mma.m16n8k16)
__device__ __forceinline__ void do_pass(float acc[4][8][4],
                                        uint32_t ra[4][4], uint32_t rb[4][4]) {
    #pragma unroll
    for (int i = 0; i < 4; i++)
        #pragma unroll
        for (int j = 0; j < 4; j++) {
            mma16816(acc[i][2 * j + 0], ra[i], &rb[j][0]);
            mma16816(acc[i][2 * j + 1], ra[i], &rb[j][2]);
        }
}

// ---------------------------------------------------------------------------
// Embedding: h[row] = tok_embd[x[row]] + pos_embd[x[row]]   (pos quirk!)
// ---------------------------------------------------------------------------
__global__ void k_embed(const int* __restrict__ x, const float* __restrict__ tok,
                        const float* __restrict__ pos, float* __restrict__ out)
{
    int row = blockIdx.x;
    int t = x[row];
    const float4* te = (const float4*)(tok + (size_t)t * Dm);
    const float4* pe = (const float4*)(pos + (size_t)t * Dm);
    float4* o = (float4*)(out + (size_t)row * Dm);
    int i = threadIdx.x;
    float4 a = te[i], b = pe[i];
    o[i] = make_float4(a.x + b.x, a.y + b.y, a.z + b.z, a.w + b.w);
}

// ---------------------------------------------------------------------------
// LayerNorm over D=1024 + fused fp16 (hi-only) output.
// ---------------------------------------------------------------------------
__global__ void k_ln(const float* __restrict__ in, const float* __restrict__ gw,
                     const float* __restrict__ bw, float* __restrict__ out,
                     __half* __restrict__ oh)
{
    __shared__ float red[8];
    int row = blockIdx.x;
    int c = threadIdx.x * 4;
    const float* xr = in + (size_t)row * Dm;
    float4 xv = *(const float4*)(xr + c);
    float s = xv.x + xv.y + xv.z + xv.w;
    #pragma unroll
    for (int o = 16; o; o >>= 1) s += __shfl_xor_sync(0xffffffffu, s, o);
    int wid = threadIdx.x >> 5, lid = threadIdx.x & 31;
    if (lid == 0) red[wid] = s;
    __syncthreads();
    float tot = 0.f;
    #pragma unroll
    for (int i = 0; i < 8; i++) tot += red[i];
    float mean = tot * (1.0f / Dm);
    float d0 = xv.x - mean, d1 = xv.y - mean, d2 = xv.z - mean, d3 = xv.w - mean;
    float s2 = d0*d0 + d1*d1 + d2*d2 + d3*d3;
    __syncthreads();
    #pragma unroll
    for (int o = 16; o; o >>= 1) s2 += __shfl_xor_sync(0xffffffffu, s2, o);
    if (lid == 0) red[wid] = s2;
    __syncthreads();
    float v2 = 0.f;
    #pragma unroll
    for (int i = 0; i < 8; i++) v2 += red[i];
    float rstd = rsqrtf(v2 * (1.0f / Dm) + 1e-5f);
    float4 gv = *(const float4*)(gw + c);
    float4 bv = *(const float4*)(bw + c);
    float4 ov = make_float4(d0 * rstd * gv.x + bv.x, d1 * rstd * gv.y + bv.y,
                            d2 * rstd * gv.z + bv.z, d3 * rstd * gv.w + bv.w);
    size_t off = (size_t)row * Dm + c;
    *(float4*)(out + off) = ov;
    *(uint32_t*)(oh + off)     = packf_h2(ov.x, ov.y);
    *(uint32_t*)(oh + off + 2) = packf_h2(ov.z, ov.w);
}

// ---------------------------------------------------------------------------
// Weight convert: qkv (H,D,HS) -> packed [3072][1024] fp16 hi/lo
// ---------------------------------------------------------------------------
__global__ void k_conv_qkv(const float* __restrict__ wq, const float* __restrict__ wk,
                           const float* __restrict__ wv,
                           __half* __restrict__ oh, __half* __restrict__ ol)
{
    __shared__ float t[64][65];
    int h = blockIdx.y;
    int d0 = blockIdx.x << 6;
    int m = blockIdx.z;
    const float* src = (m == 0) ? wq : (m == 1) ? wk : wv;

    const float* base = src + ((size_t)h << 16) + ((size_t)d0 << 6);
    for (int i = threadIdx.x; i < 1024; i += 256) {
        int di = i >> 4, e4 = (i & 15) << 2;
        float4 v = *(const float4*)(base + ((size_t)di << 6) + e4);
        t[di][e4] = v.x; t[di][e4+1] = v.y; t[di][e4+2] = v.z; t[di][e4+3] = v.w;
    }
    __syncthreads();
    for (int i = threadIdx.x; i < 2048; i += 256) {
        int e = i >> 5, d2 = (i & 31) << 1;
        __half h0, l0, h1, l1;
        split_f16(t[d2][e], h0, l0);
        split_f16(t[d2 + 1][e], h1, l1);
        size_t off = ((size_t)(m * 1024 + h * 64 + e) << 10) + d0 + d2;
        *(uint32_t*)(oh + off) = pack_h2(h0, h1);
        *(uint32_t*)(ol + off) = pack_h2(l0, l1);
    }
}

// ---------------------------------------------------------------------------
// Weight convert (transpose): in [Kd,Nd] fp32 -> out [Nd][Kd] fp16 hi/lo
// ---------------------------------------------------------------------------
__global__ void k_conv_t(const float* __restrict__ in,
                         __half* __restrict__ oh, __half* __restrict__ ol,
                         int Kd, int Nd)
{
    __shared__ float t[64][65];
    int k0 = blockIdx.y << 6, n0 = blockIdx.x << 6;
    for (int i = threadIdx.x; i < 1024; i += 256) {
        int r = i >> 4, c4 = (i & 15) << 2;
        float4 v = *(const float4*)(in + (size_t)(k0 + r) * Nd + n0 + c4);
        t[r][c4] = v.x; t[r][c4+1] = v.y; t[r][c4+2] = v.z; t[r][c4+3] = v.w;
    }
    __syncthreads();
    for (int i = threadIdx.x; i < 2048; i += 256) {
        int n = i >> 5, k2 = (i & 31) << 1;
        __half h0, l0, h1, l1;
        split_f16(t[k2][n], h0, l0);
        split_f16(t[k2 + 1][n], h1, l1);
        size_t off = (size_t)(n0 + n) * Kd + k0 + k2;
        *(uint32_t*)(oh + off) = pack_h2(h0, h1);
        *(uint32_t*)(ol + off) = pack_h2(l0, l1);
    }
}

// ---------------------------------------------------------------------------
// Tensor-core GEMM (mma.sync fp16, 2 passes):
// C[M,N] = Ah[M,K] * (Bh+Bl)^T   (A fp16 hi; B as [N][K] fp16 hi/lo)
// 128x128 CTA tile, BK=32, 128 threads (4 warps, 64x64 warp tiles),
// 2-stage cp.async double buffer; early prefetch before final pass.
// ---------------------------------------------------------------------------
#define BK 32
#define SROW 40                       // fp16 elems per smem row (80B)
#define TILE_BYTES (128 * SROW * 2)   // 10240
#define STAGE_BYTES (3 * TILE_BYTES)  // 30720 (A, Bh, Bl)
#define GEMM_SMEM (2 * STAGE_BYTES)   // 61440
#define GT 128

__device__ __forceinline__ void issue_stage(
    uint32_t sb, int stage,
    const __half* Ah, const __half* Bh, const __half* Bl,
    int m0, int n0, int kc, int K, int tid)
{
    uint32_t sbase = sb + stage * STAGE_BYTES;
    #pragma unroll
    for (int i = 0; i < 12; i++) {
        int id = (i << 7) + tid;          // 0..1535
        int tile = id >> 9;               // 0:A 1:Bh 2:Bl
        int r = (id >> 2) & 127;
        int c = id & 3;                   // 16B chunk within 64B row data
        const __half* src = (tile == 0) ? Ah : (tile == 1) ? Bh : Bl;
        int rowg = ((tile == 0) ? m0 : n0) + r;
        const void* g = src + (size_t)rowg * K + kc + (c << 3);
        uint32_t s = sbase + tile * TILE_BYTES + r * (SROW * 2) + (c << 4);
        asm volatile("cp.async.cg.shared.global [%0], [%1], 16;\n"
                     :: "r"(s), "l"(g));
    }
}

__global__ __launch_bounds__(GT, 2)
void k_gemm_mma(const __half* __restrict__ Ah,
                const __half* __restrict__ Bh, const __half* __restrict__ Bl,
                const float* __restrict__ bias, const float* __restrict__ res,
                float* __restrict__ C,
                __half* __restrict__ Ch, __half* __restrict__ Cl,
                int M, int N, int K, int relu)
{
    extern __shared__ __align__(128) char sm2[];
    uint32_t sb = smem_u32(sm2);
    int tid = threadIdx.x;
    int lane = tid & 31, wid = tid >> 5;
    int wm = (wid & 1) << 6;
    int wn = (wid >> 1) << 6;
    int m0 = blockIdx.y << 7, n0 = blockIdx.x << 7;

    float acc[4][8][4];
    #pragma unroll
    for (int i = 0; i < 4; i++)
        #pragma unroll
        for (int j = 0; j < 8; j++)
            #pragma unroll
            for (int k = 0; k < 4; k++) acc[i][j][k] = 0.f;

    issue_stage(sb, 0, Ah, Bh, Bl, m0, n0, 0, K, tid);
    asm volatile("cp.async.commit_group;\n" ::: "memory");
    issue_stage(sb, 1, Ah, Bh, Bl, m0, n0, BK, K, tid);
    asm volatile("cp.async.commit_group;\n" ::: "memory");

    int a_row = ((lane >> 3) & 1) * 8 + (lane & 7);
    int a_k   = (lane >> 4) << 3;
    int b_row = ((lane >> 4) << 3) + (lane & 7);
    int b_k   = ((lane >> 3) & 1) << 3;

    int niter = K / BK;
    for (int it = 0; it < niter; it++) {
        asm volatile("cp.async.wait_group 1;\n" ::: "memory");
        __syncthreads();
        uint32_t st = sb + (it & 1) * STAGE_BYTES;
        uint32_t ra[4][4], rbh[4][4], rbl[4][4];

        // ---- ks = 0 ----
        #pragma unroll
        for (int i = 0; i < 4; i++)
            ldsm4(ra[i], st + ((wm + i * 16 + a_row) * SROW + a_k) * 2);
        #pragma unroll
        for (int j2 = 0; j2 < 4; j2++) {
            uint32_t boff = ((wn + j2 * 16 + b_row) * SROW + b_k) * 2;
            ldsm4(rbh[j2], st + TILE_BYTES + boff);
            ldsm4(rbl[j2], st + 2 * TILE_BYTES + boff);
        }
        do_pass(acc, ra, rbh);
        do_pass(acc, ra, rbl);

        // ---- ks = 1 ----
        #pragma unroll
        for (int i = 0; i < 4; i++)
            ldsm4(ra[i], st + ((wm + i * 16 + a_row) * SROW + 16 + a_k) * 2);
        #pragma unroll
        for (int j2 = 0; j2 < 4; j2++) {
            uint32_t boff = ((wn + j2 * 16 + b_row) * SROW + 16 + b_k) * 2;
            ldsm4(rbh[j2], st + TILE_BYTES + boff);
            ldsm4(rbl[j2], st + 2 * TILE_BYTES + boff);
        }
        do_pass(acc, ra, rbh);

        // All shared reads of this stage are register-complete.
        __syncthreads();
        if (it + 2 < niter)
            issue_stage(sb, it & 1, Ah, Bh, Bl, m0, n0, (it + 2) * BK, K, tid);
        asm volatile("cp.async.commit_group;\n" ::: "memory");

        do_pass(acc, ra, rbl);    // final pass overlaps with prefetch
    }

    int g = lane >> 2, tg = (lane & 3) << 1;
    #pragma unroll
    for (int i = 0; i < 4; i++) {
        int r0 = m0 + wm + i * 16 + g;
        #pragma unroll
        for (int j = 0; j < 8; j++) {
            int col = n0 + wn + j * 8 + tg;
            float v00 = acc[i][j][0], v01 = acc[i][j][1];
            float v10 = acc[i][j][2], v11 = acc[i][j][3];
            if (bias) {
                float2 bb = *(const float2*)(bias + col);
                v00 += bb.x; v01 += bb.y; v10 += bb.x; v11 += bb.y;
            }
            if (relu) {
                v00 = fmaxf(v00, 0.f); v01 = fmaxf(v01, 0.f);
                v10 = fmaxf(v10, 0.f); v11 = fmaxf(v11, 0.f);
            }
            size_t o0 = (size_t)r0 * N + col;
            size_t o1 = o0 + (size_t)8 * N;
            if (Ch) {
                if (Cl) {
                    __half h0, l0, h1, l1;
                    split_f16(v00, h0, l0); split_f16(v01, h1, l1);
                    *(uint32_t*)(Ch + o0) = pack_h2(h0, h1);
                    *(uint32_t*)(Cl + o0) = pack_h2(l0, l1);
                    split_f16(v10, h0, l0); split_f16(v11, h1, l1);
                    *(uint32_t*)(Ch + o1) = pack_h2(h0, h1);
                    *(uint32_t*)(Cl + o1) = pack_h2(l0, l1);
                } else {
                    *(uint32_t*)(Ch + o0) = packf_h2(v00, v01);
                    *(uint32_t*)(Ch + o1) = packf_h2(v10, v11);
                }
            } else {
                if (res) {
                    float2 r0v = *(const float2*)(res + o0);
                    float2 r1v = *(const float2*)(res + o1);
                    v00 += r0v.x; v01 += r0v.y; v10 += r1v.x; v11 += r1v.y;
                }
                *(float2*)(C + o0) = make_float2(v00, v01);
                *(float2*)(C + o1) = make_float2(v10, v11);
            }
        }
    }
}

// ---------------------------------------------------------------------------
// Tensor-core causal attention (fp16, flash-style, FA2 register softmax).
// S = Qh*(Kh+Kl)^T; O += Ph*(Vh+Vl). Block = (qt, b*16+h), 128 thr / 4 warps.
// ---------------------------------------------------------------------------
#define ASROW 72                      // fp16 per smem row (144B, conflict-free)
#define ATILE (64 * ASROW * 2)        // 9216 B per tile
#define ATT_SMEM (5 * ATILE)          // Qh Kh Kl Vh Vl = 46080 B

__global__ __launch_bounds__(128)
void k_attn_tc(const __half* __restrict__ Xh, const __half* __restrict__ Xl,
               __half* __restrict__ Oh)
{
    extern __shared__ __align__(128) char smA[];
    uint32_t sb = smem_u32(smA);
    const uint32_t sQH = sb, sKH = sb + ATILE, sKL = sb + 2 * ATILE,
                   sVH = sb + 3 * ATILE, sVL = sb + 4 * ATILE;

    int qt = blockIdx.x, bh = blockIdx.y;
    int b = bh >> 4, h = bh & 15;
    int tid = threadIdx.x, lane = tid & 31, w = tid >> 5;
    size_t rbase = (size_t)b * Tm;
    int colQ = h * HSm, colK = 1024 + h * HSm, colV = 2048 + h * HSm;

    // ---- load Q tile (hi only) ----
    #pragma unroll
    for (int i = 0; i < 4; i++) {
        int id = (i << 7) + tid;          // 0..511
        int r = id >> 3, c = id & 7;
        const void* g = Xh + (rbase + qt * 64 + r) * QKVN + colQ + (c << 3);
        uint32_t s = sQH + r * (ASROW * 2) + (c << 4);
        asm volatile("cp.async.cg.shared.global [%0], [%1], 16;\n" :: "r"(s), "l"(g));
    }
    asm volatile("cp.async.commit_group;\n" ::: "memory");
    asm volatile("cp.async.wait_group 0;\n" ::: "memory");
    __syncthreads();

    int a_row = ((lane >> 3) & 1) * 8 + (lane & 7);
    int a_k   = (lane >> 4) << 3;
    uint32_t aqh[4][4];
    #pragma unroll
    for (int ks = 0; ks < 4; ks++)
        ldsm4(aqh[ks], sQH + ((w * 16 + a_row) * ASROW + ks * 16 + a_k) * 2);

    float o[8][4];
    #pragma unroll
    for (int j = 0; j < 8; j++)
        #pragma unroll
        for (int c = 0; c < 4; c++) o[j][c] = 0.f;
    float m0r = -1e30f, m1r = -1e30f, s0r = 0.f, s1r = 0.f;

    int g = lane >> 2, tg = lane & 3;
    int row0 = w * 16 + g, row1 = row0 + 8;
    int b_row = ((lane >> 4) << 3) + (lane & 7);
    int b_k   = ((lane >> 3) & 1) << 3;
    int t_row = lane & 15;
    int t_col = (lane >> 4) << 3;

    for (int kt = 0; kt <= qt; kt++) {
        __syncthreads();
        #pragma unroll
        for (int i = 0; i < 16; i++) {
            int id = (i << 7) + tid;          // 0..2047
            int tile = id >> 9;               // 0:Kh 1:Kl 2:Vh 3:Vl
            int r = (id >> 3) & 63, c = id & 7;
            const __half* src = (tile == 0 || tile == 2) ? Xh : Xl;
            int colb = (tile < 2) ? colK : colV;
            const void* gp = src + (rbase + kt * 64 + r) * QKVN + colb + (c << 3);
            uint32_t s = sKH + tile * ATILE + r * (ASROW * 2) + (c << 4);
            asm volatile("cp.async.cg.shared.global [%0], [%1], 16;\n" :: "r"(s), "l"(gp));
        }
        asm volatile("cp.async.commit_group;\n" ::: "memory");
        asm volatile("cp.async.wait_group 0;\n" ::: "memory");
        __syncthreads();

        // ---- S = Qh (Kh+Kl)^T ----
        float s[8][4];
        #pragma unroll
        for (int j = 0; j < 8; j++)
            #pragma unroll
            for (int c = 0; c < 4; c++) s[j][c] = 0.f;
        #pragma unroll
        for (int ks = 0; ks < 4; ks++) {
            uint32_t kh[4][4], kl[4][4];
            #pragma unroll
            for (int j2 = 0; j2 < 4; j2++) {
                uint32_t boff = ((j2 * 16 + b_row) * ASROW + ks * 16 + b_k) * 2;
                ldsm4(kh[j2], sKH + boff);
                ldsm4(kl[j2], sKL + boff);
            }
            #pragma unroll
            for (int j2 = 0; j2 < 4; j2++) {
                mma16816(s[2 * j2 + 0], aqh[ks], &kh[j2][0]);
                mma16816(s[2 * j2 + 1], aqh[ks], &kh[j2][2]);
            }
            #pragma unroll
            for (int j2 = 0; j2 < 4; j2++) {
                mma16816(s[2 * j2 + 0], aqh[ks], &kl[j2][0]);
                mma16816(s[2 * j2 + 1], aqh[ks], &kl[j2][2]);
            }
        }
        #pragma unroll
        for (int j = 0; j < 8; j++)
            #pragma unroll
            for (int c = 0; c < 4; c++) s[j][c] *= 0.125f;
        if (kt == qt) {
            #pragma unroll
            for (int j = 0; j < 8; j++) {
                int c0 = 8 * j + 2 * tg, c1 = c0 + 1;
                if (c0 > row0) s[j][0] = -1e30f;
                if (c1 > row0) s[j][1] = -1e30f;
                if (c0 > row1) s[j][2] = -1e30f;
                if (c1 > row1) s[j][3] = -1e30f;
            }
        }
        // ---- online softmax on register fragments ----
        float mx0 = -1e30f, mx1 = -1e30f;
        #pragma unroll
        for (int j = 0; j < 8; j++) {
            mx0 = fmaxf(mx0, fmaxf(s[j][0], s[j][1]));
            mx1 = fmaxf(mx1, fmaxf(s[j][2], s[j][3]));
        }
        mx0 = fmaxf(mx0, __shfl_xor_sync(0xffffffffu, mx0, 1));
        mx0 = fmaxf(mx0, __shfl_xor_sync(0xffffffffu, mx0, 2));
        mx1 = fmaxf(mx1, __shfl_xor_sync(0xffffffffu, mx1, 1));
        mx1 = fmaxf(mx1, __shfl_xor_sync(0xffffffffu, mx1, 2));
        mx0 = fmaxf(mx0, m0r); mx1 = fmaxf(mx1, m1r);
        float f0 = __expf(m0r - mx0), f1 = __expf(m1r - mx1);
        m0r = mx0; m1r = mx1;
        float sum0 = 0.f, sum1 = 0.f;
        #pragma unroll
        for (int j = 0; j < 8; j++) {
            s[j][0] = __expf(s[j][0] - mx0); sum0 += s[j][0];
            s[j][1] = __expf(s[j][1] - mx0); sum0 += s[j][1];
            s[j][2] = __expf(s[j][2] - mx1); sum1 += s[j][2];
            s[j][3] = __expf(s[j][3] - mx1); sum1 += s[j][3];
        }
        sum0 += __shfl_xor_sync(0xffffffffu, sum0, 1);
        sum0 += __shfl_xor_sync(0xffffffffu, sum0, 2);
        sum1 += __shfl_xor_sync(0xffffffffu, sum1, 1);
        sum1 += __shfl_xor_sync(0xffffffffu, sum1, 2);
        s0r = s0r * f0 + sum0;
        s1r = s1r * f1 + sum1;
        #pragma unroll
        for (int j = 0; j < 8; j++) {
            o[j][0] *= f0; o[j][1] *= f0; o[j][2] *= f1; o[j][3] *= f1;
        }
        // ---- O += Ph (Vh+Vl); P from S fragments (FA2 layout identity) ----
        #pragma unroll
        for (int ks = 0; ks < 4; ks++) {
            uint32_t ph[4];
            ph[0] = packf_h2(s[2 * ks][0], s[2 * ks][1]);
            ph[1] = packf_h2(s[2 * ks][2], s[2 * ks][3]);
            ph[2] = packf_h2(s[2 * ks + 1][0], s[2 * ks + 1][1]);
            ph[3] = packf_h2(s[2 * ks + 1][2], s[2 * ks + 1][3]);
            uint32_t vh[4][4], vl[4][4];
            #pragma unroll
            for (int j2 = 0; j2 < 4; j2++) {
                uint32_t voff = ((ks * 16 + t_row) * ASROW + j2 * 16 + t_col) * 2;
                ldsm4t(vh[j2], sVH + voff);
                ldsm4t(vl[j2], sVL + voff);
            }
            #pragma unroll
            for (int j2 = 0; j2 < 4; j2++) {
                mma16816(o[2 * j2 + 0], ph, &vh[j2][0]);
                mma16816(o[2 * j2 + 1], ph, &vh[j2][2]);
            }
            #pragma unroll
            for (int j2 = 0; j2 < 4; j2++) {
                mma16816(o[2 * j2 + 0], ph, &vl[j2][0]);
                mma16816(o[2 * j2 + 1], ph, &vl[j2][2]);
            }
        }
    }

    // ---- epilogue: O / s, write fp16 hi ----
    float inv0 = 1.0f / s0r, inv1 = 1.0f / s1r;
    size_t rg0 = (rbase + qt * 64 + row0) * Dm;
    size_t rg1 = (rbase + qt * 64 + row1) * Dm;
    #pragma unroll
    for (int j = 0; j < 8; j++) {
        int col = h * HSm + 8 * j + 2 * tg;
        *(uint32_t*)(Oh + rg0 + col) = packf_h2(o[j][0] * inv0, o[j][1] * inv0);
        *(uint32_t*)(Oh + rg1 + col) = packf_h2(o[j][2] * inv1, o[j][3] * inv1);
    }
}

// ---------------------------------------------------------------------------
// Host orchestration (graph-capturable: kernel launches only)
// ---------------------------------------------------------------------------
extern "C" void kernel_launch(void* const* d_in, const int* in_sizes, int n_in,
                              void* d_out, int out_size)
{
    (void)in_sizes; (void)n_in; (void)out_size;
    const int*   x      = (const int*)  d_in[0];
    const float* tok    = (const float*)d_in[1];
    const float* pos    = (const float*)d_in[2];
    const float* wq     = (const float*)d_in[3];
    const float* wk     = (const float*)d_in[4];
    const float* wv     = (const float*)d_in[5];
    const float* w_o    = (const float*)d_in[6];
    const float* b_o    = (const float*)d_in[7];
    const float* ln1_g  = (const float*)d_in[8];
    const float* ln1_b  = (const float*)d_in[9];
    const float* ln2_g  = (const float*)d_in[10];
    const float* ln2_b  = (const float*)d_in[11];
    const float* w1     = (const float*)d_in[12];
    const float* b1     = (const float*)d_in[13];
    const float* w2     = (const float*)d_in[14];
    const float* b2     = (const float*)d_in[15];
    const float* lnf_g  = (const float*)d_in[16];
    const float* lnf_b  = (const float*)d_in[17];
    const float* w_lm   = (const float*)d_in[18];
    const float* b_lm   = (const float*)d_in[19];
    float* out = (float*)d_out;

    float *hb, *hn;
    cudaGetSymbolAddress((void**)&hb, g_h);
    cudaGetSymbolAddress((void**)&hn, g_hn);

    __half *ah,*fh,*qkvh,*qkvl,*wqkvh,*wqkvl,*oh,*ol,*w1h,*w1l,*w2h,*w2l,*lh,*ll;
    cudaGetSymbolAddress((void**)&ah, g_ah);
    cudaGetSymbolAddress((void**)&fh, g_fh);
    cudaGetSymbolAddress((void**)&qkvh, g_qkvh);   cudaGetSymbolAddress((void**)&qkvl, g_qkvl);
    cudaGetSymbolAddress((void**)&wqkvh, g_wqkvh); cudaGetSymbolAddress((void**)&wqkvl, g_wqkvl);
    cudaGetSymbolAddress((void**)&oh, g_oh);       cudaGetSymbolAddress((void**)&ol, g_ol);
    cudaGetSymbolAddress((void**)&w1h, g_1h);      cudaGetSymbolAddress((void**)&w1l, g_1l);
    cudaGetSymbolAddress((void**)&w2h, g_2h);      cudaGetSymbolAddress((void**)&w2l, g_2l);
    cudaGetSymbolAddress((void**)&lh, g_lh);       cudaGetSymbolAddress((void**)&ll, g_ll);

    cudaFuncSetAttribute(k_attn_tc, cudaFuncAttributeMaxDynamicSharedMemorySize, ATT_SMEM);
    cudaFuncSetAttribute(k_gemm_mma, cudaFuncAttributeMaxDynamicSharedMemorySize, GEMM_SMEM);

    dim3 g1(Dm / 128, Mrows / 128);     // N=1024
    dim3 gq(QKVN / 128, Mrows / 128);   // N=3072
    dim3 g2(FFm / 128, Mrows / 128);    // N=4096
    dim3 gl(Vm / 128, Mrows / 128);     // N=8192
    dim3 ga(Tm / 64, Bm_ * Hm);

    k_embed<<<Mrows, 256>>>(x, tok, pos, hb);

    for (int l = 0; l < Lm; l++) {
        size_t wofs = (size_t)l * Hm * Dm * HSm;
        k_ln<<<Mrows, 256>>>(hb, ln1_g + l * Dm, ln1_b + l * Dm, hn, ah);
        k_conv_qkv<<<dim3(16, 16, 3), 256>>>(wq + wofs, wk + wofs, wv + wofs,
                                             wqkvh, wqkvl);
        // qkv (split fp16 hi+lo output)
        k_gemm_mma<<<gq, GT, GEMM_SMEM>>>(ah, wqkvh, wqkvl, nullptr, nullptr,
                                          nullptr, qkvh, qkvl, Mrows, QKVN, Dm, 0);
        k_attn_tc<<<ga, 128, ATT_SMEM>>>(qkvh, qkvl, ah);

        k_conv_t<<<dim3(16, 16), 256>>>(w_o + (size_t)l * Dm * Dm, oh, ol, Dm, Dm);
        // h = hn + att @ w_o + b_o
        k_gemm_mma<<<g1, GT, GEMM_SMEM>>>(ah, oh, ol, b_o + l * Dm, hn, hb,
                                          nullptr, nullptr, Mrows, Dm, Dm, 0);
        k_ln<<<Mrows, 256>>>(hb, ln2_g + l * Dm, ln2_b + l * Dm, hn, ah);

        k_conv_t<<<dim3(64, 16), 256>>>(w1 + (size_t)l * Dm * FFm, w1h, w1l, Dm, FFm);
        // ffn1 = relu(hn @ w1 + b1) -> fp16 hi output
        k_gemm_mma<<<g2, GT, GEMM_SMEM>>>(ah, w1h, w1l, b1 + l * FFm, nullptr,
                                          nullptr, fh, nullptr, Mrows, FFm, Dm, 1);
        k_conv_t<<<dim3(16, 64), 256>>>(w2 + (size_t)l * FFm * Dm, w2h, w2l, FFm, Dm);
        // h = hn + ffn1 @ w2 + b2
        k_gemm_mma<<<g1, GT, GEMM_SMEM>>>(fh, w2h, w2l, b2 + l * Dm, hn, hb,
                                          nullptr, nullptr, Mrows, Dm, FFm, 0);
    }

    k_ln<<<Mrows, 256>>>(hb, lnf_g, lnf_b, hn, ah);
    k_conv_t<<<dim3(128, 16), 256>>>(w_lm, lh, ll, Dm, Vm);
    k_gemm_mma<<<gl, GT, GEMM_SMEM>>>(ah, lh, ll, b_lm, nullptr, out,
                                      nullptr, nullptr, Mrows, Vm, Dm, 0);
}

// round 16
// speedup vs baseline: 3.0299x; 1.5388x over previous
#include <cuda_runtime.h>
#include <cuda_fp16.h>
#include <cstdint>

// ---------------------------------------------------------------------------
// GPT-style transformer forward. GEMMs + attention on tensor cores via
// single-pass fp16 mma.sync (A and B quantized to fp16, fp32 accumulate).
// B=4, T=1024, D=1024, H=16, HS=64, L=8, FF=4096, V=8192
// ---------------------------------------------------------------------------

#define Dm   1024
#define FFm  4096
#define Vm   8192
#define Hm   16
#define HSm  64
#define Lm   8
#define Bm_  4
#define Tm   1024
#define Mrows (Bm_ * Tm)   // 4096
#define QKVN 3072

// fp32 activation scratch
__device__ float g_h  [Mrows * Dm];
__device__ float g_hn [Mrows * Dm];

// fp16 activation scratch
__device__ __half g_ah[Mrows * Dm];            // LN out / attn out
__device__ __half g_fh[Mrows * FFm];           // FFN1 out
__device__ __half g_qkvh[Mrows * QKVN];

// fp16 weight scratch ([N][K] transposed layout), reused per layer
__device__ __half g_wqkvh[QKVN * Dm];
__device__ __half g_oh[Dm * Dm];
__device__ __half g_1h[Dm * FFm];
__device__ __half g_2h[Dm * FFm];
__device__ __half g_lh[Dm * Vm];

// ---------------------------------------------------------------------------
// helpers
// ---------------------------------------------------------------------------
__device__ __forceinline__ uint32_t smem_u32(const void* p) {
    uint32_t a;
    asm("{ .reg .u64 t; cvta.to.shared.u64 t, %1; cvt.u32.u64 %0, t; }"
        : "=r"(a) : "l"(p));
    return a;
}

__device__ __forceinline__ uint32_t packf_h2(float a, float b) {
    return (uint32_t)__half_as_ushort(__float2half_rn(a)) |
           ((uint32_t)__half_as_ushort(__float2half_rn(b)) << 16);
}

__device__ __forceinline__ void ldsm4(uint32_t* r, uint32_t addr) {
    asm volatile("ldmatrix.sync.aligned.m8n8.x4.shared.b16 {%0,%1,%2,%3}, [%4];\n"
                 : "=r"(r[0]), "=r"(r[1]), "=r"(r[2]), "=r"(r[3]) : "r"(addr));
}
__device__ __forceinline__ void ldsm4t(uint32_t* r, uint32_t addr) {
    asm volatile("ldmatrix.sync.aligned.m8n8.x4.trans.shared.b16 {%0,%1,%2,%3}, [%4];\n"
                 : "=r"(r[0]), "=r"(r[1]), "=r"(r[2]), "=r"(r[3]) : "r"(addr));
}

__device__ __forceinline__ void mma16816(float* c, const uint32_t* a, const uint32_t* b) {
    asm volatile(
        "mma.sync.aligned.m16n8k16.row.col.f32.f16.f16.f32 "
        "{%0,%1,%2,%3}, {%4,%5,%6,%7}, {%8,%9}, {%0,%1,%2,%3};\n"
        : "+f"(c[0]), "+f"(c[1]), "+f"(c[2]), "+f"(c[3])
        : "r"(a[0]), "r"(a[1]), "r"(a[2]), "r"(a[3]), "r"(b[0]), "r"(b[1]));
}

// one pass: 4 m16 tiles x 4 n16 tiles (= 32 mma.m16n8k16)
__device__ __forceinline__ void do_pass(float acc[4][8][4],
                                        uint32_t ra[4][4], uint32_t rb[4][4]) {
    #pragma unroll
    for (int i = 0; i < 4; i++)
        #pragma unroll
        for (int j = 0; j < 4; j++) {
            mma16816(acc[i][2 * j + 0], ra[i], &rb[j][0]);
            mma16816(acc[i][2 * j + 1], ra[i], &rb[j][2]);
        }
}

// ---------------------------------------------------------------------------
// Embedding: h[row] = tok_embd[x[row]] + pos_embd[x[row]]   (pos quirk!)
// ---------------------------------------------------------------------------
__global__ void k_embed(const int* __restrict__ x, const float* __restrict__ tok,
                        const float* __restrict__ pos, float* __restrict__ out)
{
    int row = blockIdx.x;
    int t = x[row];
    const float4* te = (const float4*)(tok + (size_t)t * Dm);
    const float4* pe = (const float4*)(pos + (size_t)t * Dm);
    float4* o = (float4*)(out + (size_t)row * Dm);
    int i = threadIdx.x;
    float4 a = te[i], b = pe[i];
    o[i] = make_float4(a.x + b.x, a.y + b.y, a.z + b.z, a.w + b.w);
}

// ---------------------------------------------------------------------------
// LayerNorm over D=1024 + fused fp16 output.
// ---------------------------------------------------------------------------
__global__ void k_ln(const float* __restrict__ in, const float* __restrict__ gw,
                     const float* __restrict__ bw, float* __restrict__ out,
                     __half* __restrict__ oh)
{
    __shared__ float red[8];
    int row = blockIdx.x;
    int c = threadIdx.x * 4;
    const float* xr = in + (size_t)row * Dm;
    float4 xv = *(const float4*)(xr + c);
    float s = xv.x + xv.y + xv.z + xv.w;
    #pragma unroll
    for (int o = 16; o; o >>= 1) s += __shfl_xor_sync(0xffffffffu, s, o);
    int wid = threadIdx.x >> 5, lid = threadIdx.x & 31;
    if (lid == 0) red[wid] = s;
    __syncthreads();
    float tot = 0.f;
    #pragma unroll
    for (int i = 0; i < 8; i++) tot += red[i];
    float mean = tot * (1.0f / Dm);
    float d0 = xv.x - mean, d1 = xv.y - mean, d2 = xv.z - mean, d3 = xv.w - mean;
    float s2 = d0*d0 + d1*d1 + d2*d2 + d3*d3;
    __syncthreads();
    #pragma unroll
    for (int o = 16; o; o >>= 1) s2 += __shfl_xor_sync(0xffffffffu, s2, o);
    if (lid == 0) red[wid] = s2;
    __syncthreads();
    float v2 = 0.f;
    #pragma unroll
    for (int i = 0; i < 8; i++) v2 += red[i];
    float rstd = rsqrtf(v2 * (1.0f / Dm) + 1e-5f);
    float4 gv = *(const float4*)(gw + c);
    float4 bv = *(const float4*)(bw + c);
    float4 ov = make_float4(d0 * rstd * gv.x + bv.x, d1 * rstd * gv.y + bv.y,
                            d2 * rstd * gv.z + bv.z, d3 * rstd * gv.w + bv.w);
    size_t off = (size_t)row * Dm + c;
    *(float4*)(out + off) = ov;
    *(uint32_t*)(oh + off)     = packf_h2(ov.x, ov.y);
    *(uint32_t*)(oh + off + 2) = packf_h2(ov.z, ov.w);
}

// ---------------------------------------------------------------------------
// Weight convert: qkv (H,D,HS) -> packed [3072][1024] fp16
// ---------------------------------------------------------------------------
__global__ void k_conv_qkv(const float* __restrict__ wq, const float* __restrict__ wk,
                           const float* __restrict__ wv, __half* __restrict__ oh)
{
    __shared__ float t[64][65];
    int h = blockIdx.y;
    int d0 = blockIdx.x << 6;
    int m = blockIdx.z;
    const float* src = (m == 0) ? wq : (m == 1) ? wk : wv;

    const float* base = src + ((size_t)h << 16) + ((size_t)d0 << 6);
    for (int i = threadIdx.x; i < 1024; i += 256) {
        int di = i >> 4, e4 = (i & 15) << 2;
        float4 v = *(const float4*)(base + ((size_t)di << 6) + e4);
        t[di][e4] = v.x; t[di][e4+1] = v.y; t[di][e4+2] = v.z; t[di][e4+3] = v.w;
    }
    __syncthreads();
    for (int i = threadIdx.x; i < 2048; i += 256) {
        int e = i >> 5, d2 = (i & 31) << 1;
        size_t off = ((size_t)(m * 1024 + h * 64 + e) << 10) + d0 + d2;
        *(uint32_t*)(oh + off) = packf_h2(t[d2][e], t[d2 + 1][e]);
    }
}

// ---------------------------------------------------------------------------
// Weight convert (transpose): in [Kd,Nd] fp32 -> out [Nd][Kd] fp16
// ---------------------------------------------------------------------------
__global__ void k_conv_t(const float* __restrict__ in,
                         __half* __restrict__ oh, int Kd, int Nd)
{
    __shared__ float t[64][65];
    int k0 = blockIdx.y << 6, n0 = blockIdx.x << 6;
    for (int i = threadIdx.x; i < 1024; i += 256) {
        int r = i >> 4, c4 = (i & 15) << 2;
        float4 v = *(const float4*)(in + (size_t)(k0 + r) * Nd + n0 + c4);
        t[r][c4] = v.x; t[r][c4+1] = v.y; t[r][c4+2] = v.z; t[r][c4+3] = v.w;
    }
    __syncthreads();
    for (int i = threadIdx.x; i < 2048; i += 256) {
        int n = i >> 5, k2 = (i & 31) << 1;
        size_t off = (size_t)(n0 + n) * Kd + k0 + k2;
        *(uint32_t*)(oh + off) = packf_h2(t[k2][n], t[k2 + 1][n]);
    }
}

// ---------------------------------------------------------------------------
// Tensor-core GEMM (single-pass fp16):
// C[M,N] = Ah[M,K] * Bh^T   (B as [N][K] fp16)
// 128x128 CTA tile, BK=32, 128 threads (4 warps, 64x64 warp tiles),
// 2-stage cp.async double buffer; early prefetch before final pass.
// ---------------------------------------------------------------------------
#define BK 32
#define SROW 40                       // fp16 elems per smem row (80B)
#define TILE_BYTES (128 * SROW * 2)   // 10240
#define STAGE_BYTES (2 * TILE_BYTES)  // 20480 (A, B)
#define GEMM_SMEM (2 * STAGE_BYTES)   // 40960
#define GT 128

__device__ __forceinline__ void issue_stage(
    uint32_t sb, int stage, const __half* Ah, const __half* Bh,
    int m0, int n0, int kc, int K, int tid)
{
    uint32_t sbase = sb + stage * STAGE_BYTES;
    #pragma unroll
    for (int i = 0; i < 8; i++) {
        int id = (i << 7) + tid;          // 0..1023
        int tile = id >> 9;               // 0:A 1:B
        int r = (id >> 2) & 127;
        int c = id & 3;                   // 16B chunk within 64B row data
        const __half* src = (tile == 0) ? Ah : Bh;
        int rowg = ((tile == 0) ? m0 : n0) + r;
        const void* g = src + (size_t)rowg * K + kc + (c << 3);
        uint32_t s = sbase + tile * TILE_BYTES + r * (SROW * 2) + (c << 4);
        asm volatile("cp.async.cg.shared.global [%0], [%1], 16;\n"
                     :: "r"(s), "l"(g));
    }
}

__global__ __launch_bounds__(GT, 2)
void k_gemm_mma(const __half* __restrict__ Ah, const __half* __restrict__ Bh,
                const float* __restrict__ bias, const float* __restrict__ res,
                float* __restrict__ C, __half* __restrict__ Ch,
                int M, int N, int K, int relu)
{
    extern __shared__ __align__(128) char sm2[];
    uint32_t sb = smem_u32(sm2);
    int tid = threadIdx.x;
    int lane = tid & 31, wid = tid >> 5;
    int wm = (wid & 1) << 6;
    int wn = (wid >> 1) << 6;
    int m0 = blockIdx.y << 7, n0 = blockIdx.x << 7;

    float acc[4][8][4];
    #pragma unroll
    for (int i = 0; i < 4; i++)
        #pragma unroll
        for (int j = 0; j < 8; j++)
            #pragma unroll
            for (int k = 0; k < 4; k++) acc[i][j][k] = 0.f;

    issue_stage(sb, 0, Ah, Bh, m0, n0, 0, K, tid);
    asm volatile("cp.async.commit_group;\n" ::: "memory");
    issue_stage(sb, 1, Ah, Bh, m0, n0, BK, K, tid);
    asm volatile("cp.async.commit_group;\n" ::: "memory");

    int a_row = ((lane >> 3) & 1) * 8 + (lane & 7);
    int a_k   = (lane >> 4) << 3;
    int b_row = ((lane >> 4) << 3) + (lane & 7);
    int b_k   = ((lane >> 3) & 1) << 3;

    int niter = K / BK;
    for (int it = 0; it < niter; it++) {
        asm volatile("cp.async.wait_group 1;\n" ::: "memory");
        __syncthreads();
        uint32_t st = sb + (it & 1) * STAGE_BYTES;
        uint32_t ra[4][4], rb[4][4];

        // ---- ks = 0 ----
        #pragma unroll
        for (int i = 0; i < 4; i++)
            ldsm4(ra[i], st + ((wm + i * 16 + a_row) * SROW + a_k) * 2);
        #pragma unroll
        for (int j2 = 0; j2 < 4; j2++)
            ldsm4(rb[j2], st + TILE_BYTES + ((wn + j2 * 16 + b_row) * SROW + b_k) * 2);
        do_pass(acc, ra, rb);

        // ---- ks = 1 ----
        #pragma unroll
        for (int i = 0; i < 4; i++)
            ldsm4(ra[i], st + ((wm + i * 16 + a_row) * SROW + 16 + a_k) * 2);
        #pragma unroll
        for (int j2 = 0; j2 < 4; j2++)
            ldsm4(rb[j2], st + TILE_BYTES +
                  ((wn + j2 * 16 + b_row) * SROW + 16 + b_k) * 2);

        // All shared reads of this stage are register-complete.
        __syncthreads();
        if (it + 2 < niter)
            issue_stage(sb, it & 1, Ah, Bh, m0, n0, (it + 2) * BK, K, tid);
        asm volatile("cp.async.commit_group;\n" ::: "memory");

        do_pass(acc, ra, rb);     // final pass overlaps with prefetch
    }

    int g = lane >> 2, tg = (lane & 3) << 1;
    #pragma unroll
    for (int i = 0; i < 4; i++) {
        int r0 = m0 + wm + i * 16 + g;
        #pragma unroll
        for (int j = 0; j < 8; j++) {
            int col = n0 + wn + j * 8 + tg;
            float v00 = acc[i][j][0], v01 = acc[i][j][1];
            float v10 = acc[i][j][2], v11 = acc[i][j][3];
            if (bias) {
                float2 bb = *(const float2*)(bias + col);
                v00 += bb.x; v01 += bb.y; v10 += bb.x; v11 += bb.y;
            }
            if (relu) {
                v00 = fmaxf(v00, 0.f); v01 = fmaxf(v01, 0.f);
                v10 = fmaxf(v10, 0.f); v11 = fmaxf(v11, 0.f);
            }
            size_t o0 = (size_t)r0 * N + col;
            size_t o1 = o0 + (size_t)8 * N;
            if (Ch) {
                *(uint32_t*)(Ch + o0) = packf_h2(v00, v01);
                *(uint32_t*)(Ch + o1) = packf_h2(v10, v11);
            } else {
                if (res) {
                    float2 r0v = *(const float2*)(res + o0);
                    float2 r1v = *(const float2*)(res + o1);
                    v00 += r0v.x; v01 += r0v.y; v10 += r1v.x; v11 += r1v.y;
                }
                *(float2*)(C + o0) = make_float2(v00, v01);
                *(float2*)(C + o1) = make_float2(v10, v11);
            }
        }
    }
}

// ---------------------------------------------------------------------------
// Tensor-core causal attention (fp16, flash-style, FA2 register softmax).
// S = Qh*Kh^T; O += Ph*Vh. Block = (qt, b*16+h), 128 thr / 4 warps.
// ---------------------------------------------------------------------------
#define ASROW 72                      // fp16 per smem row (144B, conflict-free)
#define ATILE (64 * ASROW * 2)        // 9216 B per tile
#define ATT_SMEM (3 * ATILE)          // Qh Kh Vh = 27648 B

__global__ __launch_bounds__(128)
void k_attn_tc(const __half* __restrict__ Xh, __half* __restrict__ Oh)
{
    extern __shared__ __align__(128) char smA[];
    uint32_t sb = smem_u32(smA);
    const uint32_t sQH = sb, sKH = sb + ATILE, sVH = sb + 2 * ATILE;

    int qt = blockIdx.x, bh = blockIdx.y;
    int b = bh >> 4, h = bh & 15;
    int tid = threadIdx.x, lane = tid & 31, w = tid >> 5;
    size_t rbase = (size_t)b * Tm;
    int colQ = h * HSm, colK = 1024 + h * HSm, colV = 2048 + h * HSm;

    // ---- load Q tile ----
    #pragma unroll
    for (int i = 0; i < 4; i++) {
        int id = (i << 7) + tid;          // 0..511
        int r = id >> 3, c = id & 7;
        const void* g = Xh + (rbase + qt * 64 + r) * QKVN + colQ + (c << 3);
        uint32_t s = sQH + r * (ASROW * 2) + (c << 4);
        asm volatile("cp.async.cg.shared.global [%0], [%1], 16;\n" :: "r"(s), "l"(g));
    }
    asm volatile("cp.async.commit_group;\n" ::: "memory");
    asm volatile("cp.async.wait_group 0;\n" ::: "memory");
    __syncthreads();

    int a_row = ((lane >> 3) & 1) * 8 + (lane & 7);
    int a_k   = (lane >> 4) << 3;
    uint32_t aqh[4][4];
    #pragma unroll
    for (int ks = 0; ks < 4; ks++)
        ldsm4(aqh[ks], sQH + ((w * 16 + a_row) * ASROW + ks * 16 + a_k) * 2);

    float o[8][4];
    #pragma unroll
    for (int j = 0; j < 8; j++)
        #pragma unroll
        for (int c = 0; c < 4; c++) o[j][c] = 0.f;
    float m0r = -1e30f, m1r = -1e30f, s0r = 0.f, s1r = 0.f;

    int g = lane >> 2, tg = lane & 3;
    int row0 = w * 16 + g, row1 = row0 + 8;
    int b_row = ((lane >> 4) << 3) + (lane & 7);
    int b_k   = ((lane >> 3) & 1) << 3;
    int t_row = lane & 15;
    int t_col = (lane >> 4) << 3;

    for (int kt = 0; kt <= qt; kt++) {
        __syncthreads();
        #pragma unroll
        for (int i = 0; i < 8; i++) {
            int id = (i << 7) + tid;          // 0..1023
            int tile = id >> 9;               // 0:Kh 1:Vh
            int r = (id >> 3) & 63, c = id & 7;
            int colb = (tile == 0) ? colK : colV;
            const void* gp = Xh + (rbase + kt * 64 + r) * QKVN + colb + (c << 3);
            uint32_t s = sKH + tile * ATILE + r * (ASROW * 2) + (c << 4);
            asm volatile("cp.async.cg.shared.global [%0], [%1], 16;\n" :: "r"(s), "l"(gp));
        }
        asm volatile("cp.async.commit_group;\n" ::: "memory");
        asm volatile("cp.async.wait_group 0;\n" ::: "memory");
        __syncthreads();

        // ---- S = Qh Kh^T ----
        float s[8][4];
        #pragma unroll
        for (int j = 0; j < 8; j++)
            #pragma unroll
            for (int c = 0; c < 4; c++) s[j][c] = 0.f;
        #pragma unroll
        for (int ks = 0; ks < 4; ks++) {
            uint32_t kh[4][4];
            #pragma unroll
            for (int j2 = 0; j2 < 4; j2++)
                ldsm4(kh[j2], sKH + ((j2 * 16 + b_row) * ASROW + ks * 16 + b_k) * 2);
            #pragma unroll
            for (int j2 = 0; j2 < 4; j2++) {
                mma16816(s[2 * j2 + 0], aqh[ks], &kh[j2][0]);
                mma16816(s[2 * j2 + 1], aqh[ks], &kh[j2][2]);
            }
        }
        #pragma unroll
        for (int j = 0; j < 8; j++)
            #pragma unroll
            for (int c = 0; c < 4; c++) s[j][c] *= 0.125f;
        if (kt == qt) {
            #pragma unroll
            for (int j = 0; j < 8; j++) {
                int c0 = 8 * j + 2 * tg, c1 = c0 + 1;
                if (c0 > row0) s[j][0] = -1e30f;
                if (c1 > row0) s[j][1] = -1e30f;
                if (c0 > row1) s[j][2] = -1e30f;
                if (c1 > row1) s[j][3] = -1e30f;
            }
        }
        // ---- online softmax on register fragments ----
        float mx0 = -1e30f, mx1 = -1e30f;
        #pragma unroll
        for (int j = 0; j < 8; j++) {
            mx0 = fmaxf(mx0, fmaxf(s[j][0], s[j][1]));
            mx1 = fmaxf(mx1, fmaxf(s[j][2], s[j][3]));
        }
        mx0 = fmaxf(mx0, __shfl_xor_sync(0xffffffffu, mx0, 1));
        mx0 = fmaxf(mx0, __shfl_xor_sync(0xffffffffu, mx0, 2));
        mx1 = fmaxf(mx1, __shfl_xor_sync(0xffffffffu, mx1, 1));
        mx1 = fmaxf(mx1, __shfl_xor_sync(0xffffffffu, mx1, 2));
        mx0 = fmaxf(mx0, m0r); mx1 = fmaxf(mx1, m1r);
        float f0 = __expf(m0r - mx0), f1 = __expf(m1r - mx1);
        m0r = mx0; m1r = mx1;
        float sum0 = 0.f, sum1 = 0.f;
        #pragma unroll
        for (int j = 0; j < 8; j++) {
            s[j][0] = __expf(s[j][0] - mx0); sum0 += s[j][0];
            s[j][1] = __expf(s[j][1] - mx0); sum0 += s[j][1];
            s[j][2] = __expf(s[j][2] - mx1); sum1 += s[j][2];
            s[j][3] = __expf(s[j][3] - mx1); sum1 += s[j][3];
        }
        sum0 += __shfl_xor_sync(0xffffffffu, sum0, 1);
        sum0 += __shfl_xor_sync(0xffffffffu, sum0, 2);
        sum1 += __shfl_xor_sync(0xffffffffu, sum1, 1);
        sum1 += __shfl_xor_sync(0xffffffffu, sum1, 2);
        s0r = s0r * f0 + sum0;
        s1r = s1r * f1 + sum1;
        #pragma unroll
        for (int j = 0; j < 8; j++) {
            o[j][0] *= f0; o[j][1] *= f0; o[j][2] *= f1; o[j][3] *= f1;
        }
        // ---- O += Ph Vh; P from S fragments (FA2 layout identity) ----
        #pragma unroll
        for (int ks = 0; ks < 4; ks++) {
            uint32_t ph[4];
            ph[0] = packf_h2(s[2 * ks][0], s[2 * ks][1]);
            ph[1] = packf_h2(s[2 * ks][2], s[2 * ks][3]);
            ph[2] = packf_h2(s[2 * ks + 1][0], s[2 * ks + 1][1]);
            ph[3] = packf_h2(s[2 * ks + 1][2], s[2 * ks + 1][3]);
            uint32_t vh[4][4];
            #pragma unroll
            for (int j2 = 0; j2 < 4; j2++)
                ldsm4t(vh[j2], sVH + ((ks * 16 + t_row) * ASROW + j2 * 16 + t_col) * 2);
            #pragma unroll
            for (int j2 = 0; j2 < 4; j2++) {
                mma16816(o[2 * j2 + 0], ph, &vh[j2][0]);
                mma16816(o[2 * j2 + 1], ph, &vh[j2][2]);
            }
        }
    }

    // ---- epilogue: O / s, write fp16 ----
    float inv0 = 1.0f / s0r, inv1 = 1.0f / s1r;
    size_t rg0 = (rbase + qt * 64 + row0) * Dm;
    size_t rg1 = (rbase + qt * 64 + row1) * Dm;
    #pragma unroll
    for (int j = 0; j < 8; j++) {
        int col = h * HSm + 8 * j + 2 * tg;
        *(uint32_t*)(Oh + rg0 + col) = packf_h2(o[j][0] * inv0, o[j][1] * inv0);
        *(uint32_t*)(Oh + rg1 + col) = packf_h2(o[j][2] * inv1, o[j][3] * inv1);
    }
}

// ---------------------------------------------------------------------------
// Host orchestration (graph-capturable: kernel launches only)
// ---------------------------------------------------------------------------
extern "C" void kernel_launch(void* const* d_in, const int* in_sizes, int n_in,
                              void* d_out, int out_size)
{
    (void)in_sizes; (void)n_in; (void)out_size;
    const int*   x      = (const int*)  d_in[0];
    const float* tok    = (const float*)d_in[1];
    const float* pos    = (const float*)d_in[2];
    const float* wq     = (const float*)d_in[3];
    const float* wk     = (const float*)d_in[4];
    const float* wv     = (const float*)d_in[5];
    const float* w_o    = (const float*)d_in[6];
    const float* b_o    = (const float*)d_in[7];
    const float* ln1_g  = (const float*)d_in[8];
    const float* ln1_b  = (const float*)d_in[9];
    const float* ln2_g  = (const float*)d_in[10];
    const float* ln2_b  = (const float*)d_in[11];
    const float* w1     = (const float*)d_in[12];
    const float* b1     = (const float*)d_in[13];
    const float* w2     = (const float*)d_in[14];
    const float* b2     = (const float*)d_in[15];
    const float* lnf_g  = (const float*)d_in[16];
    const float* lnf_b  = (const float*)d_in[17];
    const float* w_lm   = (const float*)d_in[18];
    const float* b_lm   = (const float*)d_in[19];
    float* out = (float*)d_out;

    float *hb, *hn;
    cudaGetSymbolAddress((void**)&hb, g_h);
    cudaGetSymbolAddress((void**)&hn, g_hn);

    __half *ah,*fh,*qkvh,*wqkvh,*oh,*w1h,*w2h,*lh;
    cudaGetSymbolAddress((void**)&ah, g_ah);
    cudaGetSymbolAddress((void**)&fh, g_fh);
    cudaGetSymbolAddress((void**)&qkvh, g_qkvh);
    cudaGetSymbolAddress((void**)&wqkvh, g_wqkvh);
    cudaGetSymbolAddress((void**)&oh, g_oh);
    cudaGetSymbolAddress((void**)&w1h, g_1h);
    cudaGetSymbolAddress((void**)&w2h, g_2h);
    cudaGetSymbolAddress((void**)&lh, g_lh);

    cudaFuncSetAttribute(k_attn_tc, cudaFuncAttributeMaxDynamicSharedMemorySize, ATT_SMEM);
    cudaFuncSetAttribute(k_gemm_mma, cudaFuncAttributeMaxDynamicSharedMemorySize, GEMM_SMEM);

    dim3 g1(Dm / 128, Mrows / 128);     // N=1024
    dim3 gq(QKVN / 128, Mrows / 128);   // N=3072
    dim3 g2(FFm / 128, Mrows / 128);    // N=4096
    dim3 gl(Vm / 128, Mrows / 128);     // N=8192
    dim3 ga(Tm / 64, Bm_ * Hm);

    k_embed<<<Mrows, 256>>>(x, tok, pos, hb);

    for (int l = 0; l < Lm; l++) {
        size_t wofs = (size_t)l * Hm * Dm * HSm;
        k_ln<<<Mrows, 256>>>(hb, ln1_g + l * Dm, ln1_b + l * Dm, hn, ah);
        k_conv_qkv<<<dim3(16, 16, 3), 256>>>(wq + wofs, wk + wofs, wv + wofs, wqkvh);
        // qkv (fp16 output)
        k_gemm_mma<<<gq, GT, GEMM_SMEM>>>(ah, wqkvh, nullptr, nullptr,
                                          nullptr, qkvh, Mrows, QKVN, Dm, 0);
        k_attn_tc<<<ga, 128, ATT_SMEM>>>(qkvh, ah);

        k_conv_t<<<dim3(16, 16), 256>>>(w_o + (size_t)l * Dm * Dm, oh, Dm, Dm);
        // h = hn + att @ w_o + b_o
        k_gemm_mma<<<g1, GT, GEMM_SMEM>>>(ah, oh, b_o + l * Dm, hn, hb,
                                          nullptr, Mrows, Dm, Dm, 0);
        k_ln<<<Mrows, 256>>>(hb, ln2_g + l * Dm, ln2_b + l * Dm, hn, ah);

        k_conv_t<<<dim3(64, 16), 256>>>(w1 + (size_t)l * Dm * FFm, w1h, Dm, FFm);
        // ffn1 = relu(hn @ w1 + b1) -> fp16 output
        k_gemm_mma<<<g2, GT, GEMM_SMEM>>>(ah, w1h, b1 + l * FFm, nullptr,
                                          nullptr, fh, Mrows, FFm, Dm, 1);
        k_conv_t<<<dim3(16, 64), 256>>>(w2 + (size_t)l * FFm * Dm, w2h, FFm, Dm);
        // h = hn + ffn1 @ w2 + b2
        k_gemm_mma<<<g1, GT, GEMM_SMEM>>>(fh, w2h, b2 + l * Dm, hn, hb,
                                          nullptr, Mrows, Dm, FFm, 0);
    }

    k_ln<<<Mrows, 256>>>(hb, lnf_g, lnf_b, hn, ah);
    k_conv_t<<<dim3(128, 16), 256>>>(w_lm, lh, Dm, Vm);
    k_gemm_mma<<<gl, GT, GEMM_SMEM>>>(ah, lh, b_lm, nullptr, out,
                                      nullptr, Mrows, Vm, Dm, 0);
}

// round 17
// speedup vs baseline: 3.1099x; 1.0264x over previous
#include <cuda_runtime.h>
#include <cuda_fp16.h>
#include <cstdint>

// ---------------------------------------------------------------------------
// GPT-style transformer forward. GEMMs + attention on tensor cores via
// single-pass fp16 mma.sync (A and B quantized to fp16, fp32 accumulate).
// B=4, T=1024, D=1024, H=16, HS=64, L=8, FF=4096, V=8192
// ---------------------------------------------------------------------------

#define Dm   1024
#define FFm  4096
#define Vm   8192
#define Hm   16
#define HSm  64
#define Lm   8
#define Bm_  4
#define Tm   1024
#define Mrows (Bm_ * Tm)   // 4096
#define QKVN 3072

// fp32 activation scratch
__device__ float g_h  [Mrows * Dm];
__device__ float g_hn [Mrows * Dm];

// fp16 activation scratch
__device__ __half g_ah[Mrows * Dm];            // LN out / attn out
__device__ __half g_fh[Mrows * FFm];           // FFN1 out
__device__ __half g_qkvh[Mrows * QKVN];

// fp16 weight scratch ([N][K] transposed layout), reused per layer
__device__ __half g_wqkvh[QKVN * Dm];
__device__ __half g_oh[Dm * Dm];
__device__ __half g_1h[Dm * FFm];
__device__ __half g_2h[Dm * FFm];
__device__ __half g_lh[Dm * Vm];

// ---------------------------------------------------------------------------
// helpers
// ---------------------------------------------------------------------------
__device__ __forceinline__ uint32_t smem_u32(const void* p) {
    uint32_t a;
    asm("{ .reg .u64 t; cvta.to.shared.u64 t, %1; cvt.u32.u64 %0, t; }"
        : "=r"(a) : "l"(p));
    return a;
}

__device__ __forceinline__ uint32_t packf_h2(float a, float b) {
    return (uint32_t)__half_as_ushort(__float2half_rn(a)) |
           ((uint32_t)__half_as_ushort(__float2half_rn(b)) << 16);
}

__device__ __forceinline__ void ldsm4(uint32_t* r, uint32_t addr) {
    asm volatile("ldmatrix.sync.aligned.m8n8.x4.shared.b16 {%0,%1,%2,%3}, [%4];\n"
                 : "=r"(r[0]), "=r"(r[1]), "=r"(r[2]), "=r"(r[3]) : "r"(addr));
}
__device__ __forceinline__ void ldsm4t(uint32_t* r, uint32_t addr) {
    asm volatile("ldmatrix.sync.aligned.m8n8.x4.trans.shared.b16 {%0,%1,%2,%3}, [%4];\n"
                 : "=r"(r[0]), "=r"(r[1]), "=r"(r[2]), "=r"(r[3]) : "r"(addr));
}

__device__ __forceinline__ void mma16816(float* c, const uint32_t* a, const uint32_t* b) {
    asm volatile(
        "mma.sync.aligned.m16n8k16.row.col.f32.f16.f16.f32 "
        "{%0,%1,%2,%3}, {%4,%5,%6,%7}, {%8,%9}, {%0,%1,%2,%3};\n"
        : "+f"(c[0]), "+f"(c[1]), "+f"(c[2]), "+f"(c[3])
        : "r"(a[0]), "r"(a[1]), "r"(a[2]), "r"(a[3]), "r"(b[0]), "r"(b[1]));
}

// one pass: 4 m16 tiles x 4 n16 tiles (= 32 mma.m16n8k16)
__device__ __forceinline__ void do_pass(float acc[4][8][4],
                                        uint32_t ra[4][4], uint32_t rb[4][4]) {
    #pragma unroll
    for (int i = 0; i < 4; i++)
        #pragma unroll
        for (int j = 0; j < 4; j++) {
            mma16816(acc[i][2 * j + 0], ra[i], &rb[j][0]);
            mma16816(acc[i][2 * j + 1], ra[i], &rb[j][2]);
        }
}

// ---------------------------------------------------------------------------
// Embedding: h[row] = tok_embd[x[row]] + pos_embd[x[row]]   (pos quirk!)
// ---------------------------------------------------------------------------
__global__ void k_embed(const int* __restrict__ x, const float* __restrict__ tok,
                        const float* __restrict__ pos, float* __restrict__ out)
{
    int row = blockIdx.x;
    int t = x[row];
    const float4* te = (const float4*)(tok + (size_t)t * Dm);
    const float4* pe = (const float4*)(pos + (size_t)t * Dm);
    float4* o = (float4*)(out + (size_t)row * Dm);
    int i = threadIdx.x;
    float4 a = te[i], b = pe[i];
    o[i] = make_float4(a.x + b.x, a.y + b.y, a.z + b.z, a.w + b.w);
}

// ---------------------------------------------------------------------------
// LayerNorm over D=1024 + fused fp16 output.
// ---------------------------------------------------------------------------
__global__ void k_ln(const float* __restrict__ in, const float* __restrict__ gw,
                     const float* __restrict__ bw, float* __restrict__ out,
                     __half* __restrict__ oh)
{
    __shared__ float red[8];
    int row = blockIdx.x;
    int c = threadIdx.x * 4;
    const float* xr = in + (size_t)row * Dm;
    float4 xv = *(const float4*)(xr + c);
    float s = xv.x + xv.y + xv.z + xv.w;
    #pragma unroll
    for (int o = 16; o; o >>= 1) s += __shfl_xor_sync(0xffffffffu, s, o);
    int wid = threadIdx.x >> 5, lid = threadIdx.x & 31;
    if (lid == 0) red[wid] = s;
    __syncthreads();
    float tot = 0.f;
    #pragma unroll
    for (int i = 0; i < 8; i++) tot += red[i];
    float mean = tot * (1.0f / Dm);
    float d0 = xv.x - mean, d1 = xv.y - mean, d2 = xv.z - mean, d3 = xv.w - mean;
    float s2 = d0*d0 + d1*d1 + d2*d2 + d3*d3;
    __syncthreads();
    #pragma unroll
    for (int o = 16; o; o >>= 1) s2 += __shfl_xor_sync(0xffffffffu, s2, o);
    if (lid == 0) red[wid] = s2;
    __syncthreads();
    float v2 = 0.f;
    #pragma unroll
    for (int i = 0; i < 8; i++) v2 += red[i];
    float rstd = rsqrtf(v2 * (1.0f / Dm) + 1e-5f);
    float4 gv = *(const float4*)(gw + c);
    float4 bv = *(const float4*)(bw + c);
    float4 ov = make_float4(d0 * rstd * gv.x + bv.x, d1 * rstd * gv.y + bv.y,
                            d2 * rstd * gv.z + bv.z, d3 * rstd * gv.w + bv.w);
    size_t off = (size_t)row * Dm + c;
    *(float4*)(out + off) = ov;
    *(uint32_t*)(oh + off)     = packf_h2(ov.x, ov.y);
    *(uint32_t*)(oh + off + 2) = packf_h2(ov.z, ov.w);
}

// ---------------------------------------------------------------------------
// Weight convert: qkv (H,D,HS) -> packed [3072][1024] fp16
// ---------------------------------------------------------------------------
__global__ void k_conv_qkv(const float* __restrict__ wq, const float* __restrict__ wk,
                           const float* __restrict__ wv, __half* __restrict__ oh)
{
    __shared__ float t[64][65];
    int h = blockIdx.y;
    int d0 = blockIdx.x << 6;
    int m = blockIdx.z;
    const float* src = (m == 0) ? wq : (m == 1) ? wk : wv;

    const float* base = src + ((size_t)h << 16) + ((size_t)d0 << 6);
    for (int i = threadIdx.x; i < 1024; i += 256) {
        int di = i >> 4, e4 = (i & 15) << 2;
        float4 v = *(const float4*)(base + ((size_t)di << 6) + e4);
        t[di][e4] = v.x; t[di][e4+1] = v.y; t[di][e4+2] = v.z; t[di][e4+3] = v.w;
    }
    __syncthreads();
    for (int i = threadIdx.x; i < 2048; i += 256) {
        int e = i >> 5, d2 = (i & 31) << 1;
        size_t off = ((size_t)(m * 1024 + h * 64 + e) << 10) + d0 + d2;
        *(uint32_t*)(oh + off) = packf_h2(t[d2][e], t[d2 + 1][e]);
    }
}

// ---------------------------------------------------------------------------
// Weight convert (transpose): in [Kd,Nd] fp32 -> out [Nd][Kd] fp16
// ---------------------------------------------------------------------------
__global__ void k_conv_t(const float* __restrict__ in,
                         __half* __restrict__ oh, int Kd, int Nd)
{
    __shared__ float t[64][65];
    int k0 = blockIdx.y << 6, n0 = blockIdx.x << 6;
    for (int i = threadIdx.x; i < 1024; i += 256) {
        int r = i >> 4, c4 = (i & 15) << 2;
        float4 v = *(const float4*)(in + (size_t)(k0 + r) * Nd + n0 + c4);
        t[r][c4] = v.x; t[r][c4+1] = v.y; t[r][c4+2] = v.z; t[r][c4+3] = v.w;
    }
    __syncthreads();
    for (int i = threadIdx.x; i < 2048; i += 256) {
        int n = i >> 5, k2 = (i & 31) << 1;
        size_t off = (size_t)(n0 + n) * Kd + k0 + k2;
        *(uint32_t*)(oh + off) = packf_h2(t[k2][n], t[k2 + 1][n]);
    }
}

// ---------------------------------------------------------------------------
// Tensor-core GEMM (single-pass fp16):
// C[M,N] = Ah[M,K] * Bh^T   (B as [N][K] fp16)
// 128x128 CTA tile, BK=64, 128 threads (4 warps, 64x64 warp tiles),
// 2-stage cp.async double buffer; early prefetch before final pass.
// SROW=72 (144B rows): 16B-aligned, ldmatrix conflict-free (16r mod 128).
// ---------------------------------------------------------------------------
#define BK 64
#define SROW 72                       // fp16 elems per smem row (144B)
#define TILE_BYTES (128 * SROW * 2)   // 18432
#define STAGE_BYTES (2 * TILE_BYTES)  // 36864 (A, B)
#define GEMM_SMEM (2 * STAGE_BYTES)   // 73728
#define GT 128

__device__ __forceinline__ void issue_stage(
    uint32_t sb, int stage, const __half* Ah, const __half* Bh,
    int m0, int n0, int kc, int K, int tid)
{
    uint32_t sbase = sb + stage * STAGE_BYTES;
    #pragma unroll
    for (int i = 0; i < 16; i++) {
        int id = (i << 7) + tid;          // 0..2047
        int tile = id >> 10;              // 0:A 1:B
        int r = (id >> 3) & 127;
        int c = id & 7;                   // 16B chunk within 128B row data
        const __half* src = (tile == 0) ? Ah : Bh;
        int rowg = ((tile == 0) ? m0 : n0) + r;
        const void* g = src + (size_t)rowg * K + kc + (c << 3);
        uint32_t s = sbase + tile * TILE_BYTES + r * (SROW * 2) + (c << 4);
        asm volatile("cp.async.cg.shared.global [%0], [%1], 16;\n"
                     :: "r"(s), "l"(g));
    }
}

__global__ __launch_bounds__(GT, 2)
void k_gemm_mma(const __half* __restrict__ Ah, const __half* __restrict__ Bh,
                const float* __restrict__ bias, const float* __restrict__ res,
                float* __restrict__ C, __half* __restrict__ Ch,
                int M, int N, int K, int relu)
{
    extern __shared__ __align__(128) char sm2[];
    uint32_t sb = smem_u32(sm2);
    int tid = threadIdx.x;
    int lane = tid & 31, wid = tid >> 5;
    int wm = (wid & 1) << 6;
    int wn = (wid >> 1) << 6;
    int m0 = blockIdx.y << 7, n0 = blockIdx.x << 7;

    float acc[4][8][4];
    #pragma unroll
    for (int i = 0; i < 4; i++)
        #pragma unroll
        for (int j = 0; j < 8; j++)
            #pragma unroll
            for (int k = 0; k < 4; k++) acc[i][j][k] = 0.f;

    issue_stage(sb, 0, Ah, Bh, m0, n0, 0, K, tid);
    asm volatile("cp.async.commit_group;\n" ::: "memory");
    issue_stage(sb, 1, Ah, Bh, m0, n0, BK, K, tid);
    asm volatile("cp.async.commit_group;\n" ::: "memory");

    int a_row = ((lane >> 3) & 1) * 8 + (lane & 7);
    int a_k   = (lane >> 4) << 3;
    int b_row = ((lane >> 4) << 3) + (lane & 7);
    int b_k   = ((lane >> 3) & 1) << 3;

    int niter = K / BK;
    for (int it = 0; it < niter; it++) {
        asm volatile("cp.async.wait_group 1;\n" ::: "memory");
        __syncthreads();
        uint32_t st = sb + (it & 1) * STAGE_BYTES;
        uint32_t ra[4][4], rb[4][4];

        // ---- ks = 0..2 ----
        #pragma unroll
        for (int ks = 0; ks < 3; ks++) {
            #pragma unroll
            for (int i = 0; i < 4; i++)
                ldsm4(ra[i], st + ((wm + i * 16 + a_row) * SROW + ks * 16 + a_k) * 2);
            #pragma unroll
            for (int j2 = 0; j2 < 4; j2++)
                ldsm4(rb[j2], st + TILE_BYTES +
                      ((wn + j2 * 16 + b_row) * SROW + ks * 16 + b_k) * 2);
            do_pass(acc, ra, rb);
        }

        // ---- ks = 3: load, then prefetch, then MMA (overlap) ----
        #pragma unroll
        for (int i = 0; i < 4; i++)
            ldsm4(ra[i], st + ((wm + i * 16 + a_row) * SROW + 48 + a_k) * 2);
        #pragma unroll
        for (int j2 = 0; j2 < 4; j2++)
            ldsm4(rb[j2], st + TILE_BYTES +
                  ((wn + j2 * 16 + b_row) * SROW + 48 + b_k) * 2);

        __syncthreads();
        if (it + 2 < niter)
            issue_stage(sb, it & 1, Ah, Bh, m0, n0, (it + 2) * BK, K, tid);
        asm volatile("cp.async.commit_group;\n" ::: "memory");

        do_pass(acc, ra, rb);     // final pass overlaps with prefetch
    }

    int g = lane >> 2, tg = (lane & 3) << 1;
    #pragma unroll
    for (int i = 0; i < 4; i++) {
        int r0 = m0 + wm + i * 16 + g;
        #pragma unroll
        for (int j = 0; j < 8; j++) {
            int col = n0 + wn + j * 8 + tg;
            float v00 = acc[i][j][0], v01 = acc[i][j][1];
            float v10 = acc[i][j][2], v11 = acc[i][j][3];
            if (bias) {
                float2 bb = *(const float2*)(bias + col);
                v00 += bb.x; v01 += bb.y; v10 += bb.x; v11 += bb.y;
            }
            if (relu) {
                v00 = fmaxf(v00, 0.f); v01 = fmaxf(v01, 0.f);
                v10 = fmaxf(v10, 0.f); v11 = fmaxf(v11, 0.f);
            }
            size_t o0 = (size_t)r0 * N + col;
            size_t o1 = o0 + (size_t)8 * N;
            if (Ch) {
                *(uint32_t*)(Ch + o0) = packf_h2(v00, v01);
                *(uint32_t*)(Ch + o1) = packf_h2(v10, v11);
            } else {
                if (res) {
                    float2 r0v = *(const float2*)(res + o0);
                    float2 r1v = *(const float2*)(res + o1);
                    v00 += r0v.x; v01 += r0v.y; v10 += r1v.x; v11 += r1v.y;
                }
                *(float2*)(C + o0) = make_float2(v00, v01);
                *(float2*)(C + o1) = make_float2(v10, v11);
            }
        }
    }
}

// ---------------------------------------------------------------------------
// Tensor-core causal attention (fp16, flash-style, FA2 register softmax).
// S = Qh*Kh^T; O += Ph*Vh. Block = (qt, b*16+h), 128 thr / 4 warps.
// ---------------------------------------------------------------------------
#define ASROW 72                      // fp16 per smem row (144B, conflict-free)
#define ATILE (64 * ASROW * 2)        // 9216 B per tile
#define ATT_SMEM (3 * ATILE)          // Qh Kh Vh = 27648 B

__global__ __launch_bounds__(128)
void k_attn_tc(const __half* __restrict__ Xh, __half* __restrict__ Oh)
{
    extern __shared__ __align__(128) char smA[];
    uint32_t sb = smem_u32(smA);
    const uint32_t sQH = sb, sKH = sb + ATILE, sVH = sb + 2 * ATILE;

    int qt = blockIdx.x, bh = blockIdx.y;
    int b = bh >> 4, h = bh & 15;
    int tid = threadIdx.x, lane = tid & 31, w = tid >> 5;
    size_t rbase = (size_t)b * Tm;
    int colQ = h * HSm, colK = 1024 + h * HSm, colV = 2048 + h * HSm;

    // ---- load Q tile ----
    #pragma unroll
    for (int i = 0; i < 4; i++) {
        int id = (i << 7) + tid;          // 0..511
        int r = id >> 3, c = id & 7;
        const void* g = Xh + (rbase + qt * 64 + r) * QKVN + colQ + (c << 3);
        uint32_t s = sQH + r * (ASROW * 2) + (c << 4);
        asm volatile("cp.async.cg.shared.global [%0], [%1], 16;\n" :: "r"(s), "l"(g));
    }
    asm volatile("cp.async.commit_group;\n" ::: "memory");
    asm volatile("cp.async.wait_group 0;\n" ::: "memory");
    __syncthreads();

    int a_row = ((lane >> 3) & 1) * 8 + (lane & 7);
    int a_k   = (lane >> 4) << 3;
    uint32_t aqh[4][4];
    #pragma unroll
    for (int ks = 0; ks < 4; ks++)
        ldsm4(aqh[ks], sQH + ((w * 16 + a_row) * ASROW + ks * 16 + a_k) * 2);

    float o[8][4];
    #pragma unroll
    for (int j = 0; j < 8; j++)
        #pragma unroll
        for (int c = 0; c < 4; c++) o[j][c] = 0.f;
    float m0r = -1e30f, m1r = -1e30f, s0r = 0.f, s1r = 0.f;

    int g = lane >> 2, tg = lane & 3;
    int row0 = w * 16 + g, row1 = row0 + 8;
    int b_row = ((lane >> 4) << 3) + (lane & 7);
    int b_k   = ((lane >> 3) & 1) << 3;
    int t_row = lane & 15;
    int t_col = (lane >> 4) << 3;

    for (int kt = 0; kt <= qt; kt++) {
        __syncthreads();
        #pragma unroll
        for (int i = 0; i < 8; i++) {
            int id = (i << 7) + tid;          // 0..1023
            int tile = id >> 9;               // 0:Kh 1:Vh
            int r = (id >> 3) & 63, c = id & 7;
            int colb = (tile == 0) ? colK : colV;
            const void* gp = Xh + (rbase + kt * 64 + r) * QKVN + colb + (c << 3);
            uint32_t s = sKH + tile * ATILE + r * (ASROW * 2) + (c << 4);
            asm volatile("cp.async.cg.shared.global [%0], [%1], 16;\n" :: "r"(s), "l"(gp));
        }
        asm volatile("cp.async.commit_group;\n" ::: "memory");
        asm volatile("cp.async.wait_group 0;\n" ::: "memory");
        __syncthreads();

        // ---- S = Qh Kh^T ----
        float s[8][4];
        #pragma unroll
        for (int j = 0; j < 8; j++)
            #pragma unroll
            for (int c = 0; c < 4; c++) s[j][c] = 0.f;
        #pragma unroll
        for (int ks = 0; ks < 4; ks++) {
            uint32_t kh[4][4];
            #pragma unroll
            for (int j2 = 0; j2 < 4; j2++)
                ldsm4(kh[j2], sKH + ((j2 * 16 + b_row) * ASROW + ks * 16 + b_k) * 2);
            #pragma unroll
            for (int j2 = 0; j2 < 4; j2++) {
                mma16816(s[2 * j2 + 0], aqh[ks], &kh[j2][0]);
                mma16816(s[2 * j2 + 1], aqh[ks], &kh[j2][2]);
            }
        }
        #pragma unroll
        for (int j = 0; j < 8; j++)
            #pragma unroll
            for (int c = 0; c < 4; c++) s[j][c] *= 0.125f;
        if (kt == qt) {
            #pragma unroll
            for (int j = 0; j < 8; j++) {
                int c0 = 8 * j + 2 * tg, c1 = c0 + 1;
                if (c0 > row0) s[j][0] = -1e30f;
                if (c1 > row0) s[j][1] = -1e30f;
                if (c0 > row1) s[j][2] = -1e30f;
                if (c1 > row1) s[j][3] = -1e30f;
            }
        }
        // ---- online softmax on register fragments ----
        float mx0 = -1e30f, mx1 = -1e30f;
        #pragma unroll
        for (int j = 0; j < 8; j++) {
            mx0 = fmaxf(mx0, fmaxf(s[j][0], s[j][1]));
            mx1 = fmaxf(mx1, fmaxf(s[j][2], s[j][3]));
        }
        mx0 = fmaxf(mx0, __shfl_xor_sync(0xffffffffu, mx0, 1));
        mx0 = fmaxf(mx0, __shfl_xor_sync(0xffffffffu, mx0, 2));
        mx1 = fmaxf(mx1, __shfl_xor_sync(0xffffffffu, mx1, 1));
        mx1 = fmaxf(mx1, __shfl_xor_sync(0xffffffffu, mx1, 2));
        mx0 = fmaxf(mx0, m0r); mx1 = fmaxf(mx1, m1r);
        float f0 = __expf(m0r - mx0), f1 = __expf(m1r - mx1);
        m0r = mx0; m1r = mx1;
        float sum0 = 0.f, sum1 = 0.f;
        #pragma unroll
        for (int j = 0; j < 8; j++) {
            s[j][0] = __expf(s[j][0] - mx0); sum0 += s[j][0];
            s[j][1] = __expf(s[j][1] - mx0); sum0 += s[j][1];
            s[j][2] = __expf(s[j][2] - mx1); sum1 += s[j][2];
            s[j][3] = __expf(s[j][3] - mx1); sum1 += s[j][3];
        }
        sum0 += __shfl_xor_sync(0xffffffffu, sum0, 1);
        sum0 += __shfl_xor_sync(0xffffffffu, sum0, 2);
        sum1 += __shfl_xor_sync(0xffffffffu, sum1, 1);
        sum1 += __shfl_xor_sync(0xffffffffu, sum1, 2);
        s0r = s0r * f0 + sum0;
        s1r = s1r * f1 + sum1;
        #pragma unroll
        for (int j = 0; j < 8; j++) {
            o[j][0] *= f0; o[j][1] *= f0; o[j][2] *= f1; o[j][3] *= f1;
        }
        // ---- O += Ph Vh; P from S fragments (FA2 layout identity) ----
        #pragma unroll
        for (int ks = 0; ks < 4; ks++) {
            uint32_t ph[4];
            ph[0] = packf_h2(s[2 * ks][0], s[2 * ks][1]);
            ph[1] = packf_h2(s[2 * ks][2], s[2 * ks][3]);
            ph[2] = packf_h2(s[2 * ks + 1][0], s[2 * ks + 1][1]);
            ph[3] = packf_h2(s[2 * ks + 1][2], s[2 * ks + 1][3]);
            uint32_t vh[4][4];
            #pragma unroll
            for (int j2 = 0; j2 < 4; j2++)
                ldsm4t(vh[j2], sVH + ((ks * 16 + t_row) * ASROW + j2 * 16 + t_col) * 2);
            #pragma unroll
            for (int j2 = 0; j2 < 4; j2++) {
                mma16816(o[2 * j2 + 0], ph, &vh[j2][0]);
                mma16816(o[2 * j2 + 1], ph, &vh[j2][2]);
            }
        }
    }

    // ---- epilogue: O / s, write fp16 ----
    float inv0 = 1.0f / s0r, inv1 = 1.0f / s1r;
    size_t rg0 = (rbase + qt * 64 + row0) * Dm;
    size_t rg1 = (rbase + qt * 64 + row1) * Dm;
    #pragma unroll
    for (int j = 0; j < 8; j++) {
        int col = h * HSm + 8 * j + 2 * tg;
        *(uint32_t*)(Oh + rg0 + col) = packf_h2(o[j][0] * inv0, o[j][1] * inv0);
        *(uint32_t*)(Oh + rg1 + col) = packf_h2(o[j][2] * inv1, o[j][3] * inv1);
    }
}

// ---------------------------------------------------------------------------
// Host orchestration (graph-capturable: kernel launches only)
// ---------------------------------------------------------------------------
extern "C" void kernel_launch(void* const* d_in, const int* in_sizes, int n_in,
                              void* d_out, int out_size)
{
    (void)in_sizes; (void)n_in; (void)out_size;
    const int*   x      = (const int*)  d_in[0];
    const float* tok    = (const float*)d_in[1];
    const float* pos    = (const float*)d_in[2];
    const float* wq     = (const float*)d_in[3];
    const float* wk     = (const float*)d_in[4];
    const float* wv     = (const float*)d_in[5];
    const float* w_o    = (const float*)d_in[6];
    const float* b_o    = (const float*)d_in[7];
    const float* ln1_g  = (const float*)d_in[8];
    const float* ln1_b  = (const float*)d_in[9];
    const float* ln2_g  = (const float*)d_in[10];
    const float* ln2_b  = (const float*)d_in[11];
    const float* w1     = (const float*)d_in[12];
    const float* b1     = (const float*)d_in[13];
    const float* w2     = (const float*)d_in[14];
    const float* b2     = (const float*)d_in[15];
    const float* lnf_g  = (const float*)d_in[16];
    const float* lnf_b  = (const float*)d_in[17];
    const float* w_lm   = (const float*)d_in[18];
    const float* b_lm   = (const float*)d_in[19];
    float* out = (float*)d_out;

    float *hb, *hn;
    cudaGetSymbolAddress((void**)&hb, g_h);
    cudaGetSymbolAddress((void**)&hn, g_hn);

    __half *ah,*fh,*qkvh,*wqkvh,*oh,*w1h,*w2h,*lh;
    cudaGetSymbolAddress((void**)&ah, g_ah);
    cudaGetSymbolAddress((void**)&fh, g_fh);
    cudaGetSymbolAddress((void**)&qkvh, g_qkvh);
    cudaGetSymbolAddress((void**)&wqkvh, g_wqkvh);
    cudaGetSymbolAddress((void**)&oh, g_oh);
    cudaGetSymbolAddress((void**)&w1h, g_1h);
    cudaGetSymbolAddress((void**)&w2h, g_2h);
    cudaGetSymbolAddress((void**)&lh, g_lh);

    cudaFuncSetAttribute(k_attn_tc, cudaFuncAttributeMaxDynamicSharedMemorySize, ATT_SMEM);
    cudaFuncSetAttribute(k_gemm_mma, cudaFuncAttributeMaxDynamicSharedMemorySize, GEMM_SMEM);

    dim3 g1(Dm / 128, Mrows / 128);     // N=1024
    dim3 gq(QKVN / 128, Mrows / 128);   // N=3072
    dim3 g2(FFm / 128, Mrows / 128);    // N=4096
    dim3 gl(Vm / 128, Mrows / 128);     // N=8192
    dim3 ga(Tm / 64, Bm_ * Hm);

    k_embed<<<Mrows, 256>>>(x, tok, pos, hb);

    for (int l = 0; l < Lm; l++) {
        size_t wofs = (size_t)l * Hm * Dm * HSm;
        k_ln<<<Mrows, 256>>>(hb, ln1_g + l * Dm, ln1_b + l * Dm, hn, ah);
        k_conv_qkv<<<dim3(16, 16, 3), 256>>>(wq + wofs, wk + wofs, wv + wofs, wqkvh);
        // qkv (fp16 output)
        k_gemm_mma<<<gq, GT, GEMM_SMEM>>>(ah, wqkvh, nullptr, nullptr,
                                          nullptr, qkvh, Mrows, QKVN, Dm, 0);
        k_attn_tc<<<ga, 128, ATT_SMEM>>>(qkvh, ah);

        k_conv_t<<<dim3(16, 16), 256>>>(w_o + (size_t)l * Dm * Dm, oh, Dm, Dm);
        // h = hn + att @ w_o + b_o
        k_gemm_mma<<<g1, GT, GEMM_SMEM>>>(ah, oh, b_o + l * Dm, hn, hb,
                                          nullptr, Mrows, Dm, Dm, 0);
        k_ln<<<Mrows, 256>>>(hb, ln2_g + l * Dm, ln2_b + l * Dm, hn, ah);

        k_conv_t<<<dim3(64, 16), 256>>>(w1 + (size_t)l * Dm * FFm, w1h, Dm, FFm);
        // ffn1 = relu(hn @ w1 + b1) -> fp16 output
        k_gemm_mma<<<g2, GT, GEMM_SMEM>>>(ah, w1h, b1 + l * FFm, nullptr,
                                          nullptr, fh, Mrows, FFm, Dm, 1);
        k_conv_t<<<dim3(16, 64), 256>>>(w2 + (size_t)l * FFm * Dm, w2h, FFm, Dm);
        // h = hn + ffn1 @ w2 + b2
        k_gemm_mma<<<g1, GT, GEMM_SMEM>>>(fh, w2h, b2 + l * Dm, hn, hb,
                                          nullptr, Mrows, Dm, FFm, 0);
    }

    k_ln<<<Mrows, 256>>>(hb, lnf_g, lnf_b, hn, ah);
    k_conv_t<<<dim3(128, 16), 256>>>(w_lm, lh, Dm, Vm);
    k_gemm_mma<<<gl, GT, GEMM_SMEM>>>(ah, lh, b_lm, nullptr, out,
                                      nullptr, Mrows, Vm, Dm, 0);
}